// round 4
// baseline (speedup 1.0000x reference)
#include <cuda_runtime.h>
#include <cuda_bf16.h>

#define BB 4
#define HH 8
#define SS 2048
#define DM 512
#define DH 64

// ---- scratch (static device allocs: allowed; cudaMalloc is not) ----
__device__ float g_Qp[BB*SS*DM];
__device__ float g_Kp[BB*SS*DM];
__device__ float g_Vp[BB*SS*DM];
__device__ float g_ctx[BB*SS*DM];
__device__ float g_x[BB*SS*DM];
__device__ int   g_mask_mode;   // 0=uint8, 1=float32, 2=int32

// ============================================================================
// Detect on-device dtype of the bool attention_mask (see R2 notes).
// ============================================================================
__global__ void detect_mask_mode(const unsigned int* __restrict__ m) {
    if (threadIdx.x == 0) {
        bool f01 = true, i01 = true;
        for (int i = 0; i < 1024; ++i) {
            const unsigned int w = m[i];
            if (w != 0u && w != 0x3F800000u) f01 = false;
            if (w != 0u && w != 1u)          i01 = false;
        }
        g_mask_mode = f01 ? 1 : (i01 ? 2 : 0);
    }
}

// ============================================================================
// fp32 SIMT GEMM: C[M,512] = A @ W^T (+resid). Near fp32 roofline (ncu: 157us).
// ============================================================================
__global__ __launch_bounds__(256) void gemm512(
        const float* __restrict__ A, const float* __restrict__ W,
        const float* __restrict__ resid, float* __restrict__ C) {
    __shared__ float As[64][17];
    __shared__ float Ws[64][17];
    const int m0 = blockIdx.y * 64;
    const int n0 = blockIdx.x * 64;
    const int t  = threadIdx.x;
    const int tx = t & 15, ty = t >> 4;
    const int lrow = t >> 2, lc4 = (t & 3) << 2;
    float acc[4][4] = {};
    for (int k0 = 0; k0 < 512; k0 += 16) {
        float4 av = *(const float4*)(A + (size_t)(m0 + lrow) * 512 + k0 + lc4);
        float4 wv = *(const float4*)(W + (size_t)(n0 + lrow) * 512 + k0 + lc4);
        As[lrow][lc4+0] = av.x; As[lrow][lc4+1] = av.y;
        As[lrow][lc4+2] = av.z; As[lrow][lc4+3] = av.w;
        Ws[lrow][lc4+0] = wv.x; Ws[lrow][lc4+1] = wv.y;
        Ws[lrow][lc4+2] = wv.z; Ws[lrow][lc4+3] = wv.w;
        __syncthreads();
        #pragma unroll
        for (int kk = 0; kk < 16; ++kk) {
            float a[4], bv[4];
            #pragma unroll
            for (int i = 0; i < 4; ++i) a[i] = As[ty + 16*i][kk];
            #pragma unroll
            for (int j = 0; j < 4; ++j) bv[j] = Ws[tx + 16*j][kk];
            #pragma unroll
            for (int i = 0; i < 4; ++i)
                #pragma unroll
                for (int j = 0; j < 4; ++j)
                    acc[i][j] = fmaf(a[i], bv[j], acc[i][j]);
        }
        __syncthreads();
    }
    #pragma unroll
    for (int i = 0; i < 4; ++i) {
        const int m = m0 + ty + 16*i;
        #pragma unroll
        for (int j = 0; j < 4; ++j) {
            const int n = n0 + tx + 16*j;
            float v = acc[i][j];
            if (resid) v += resid[(size_t)m * 512 + n];
            C[(size_t)m * 512 + n] = v;
        }
    }
}

// ---------------------------------------------------------------------------
// mma.sync helpers
// ---------------------------------------------------------------------------
__device__ __forceinline__ unsigned int f2tf32(float x) {
    unsigned int u;
    asm("cvt.rna.tf32.f32 %0, %1;" : "=r"(u) : "f"(x));
    return u;
}
__device__ __forceinline__ unsigned int pack_bf16(float lo, float hi) {
    unsigned int u;
    asm("cvt.rn.bf16x2.f32 %0, %1, %2;" : "=r"(u) : "f"(hi), "f"(lo));
    return u;
}
__device__ __forceinline__ void mma_tf32(float& c0, float& c1, float& c2, float& c3,
        unsigned int a0, unsigned int a1, unsigned int a2, unsigned int a3,
        unsigned int b0, unsigned int b1) {
    asm volatile(
        "mma.sync.aligned.m16n8k8.row.col.f32.tf32.tf32.f32 "
        "{%0,%1,%2,%3}, {%4,%5,%6,%7}, {%8,%9}, {%0,%1,%2,%3};\n"
        : "+f"(c0), "+f"(c1), "+f"(c2), "+f"(c3)
        : "r"(a0), "r"(a1), "r"(a2), "r"(a3), "r"(b0), "r"(b1));
}
__device__ __forceinline__ void mma_bf16(float& c0, float& c1, float& c2, float& c3,
        unsigned int a0, unsigned int a1, unsigned int a2, unsigned int a3,
        unsigned int b0, unsigned int b1) {
    asm volatile(
        "mma.sync.aligned.m16n8k16.row.col.f32.bf16.bf16.f32 "
        "{%0,%1,%2,%3}, {%4,%5,%6,%7}, {%8,%9}, {%0,%1,%2,%3};\n"
        : "+f"(c0), "+f"(c1), "+f"(c2), "+f"(c3)
        : "r"(a0), "r"(a1), "r"(a2), "r"(a3), "r"(b0), "r"(b1));
}

__device__ __forceinline__ void mask_pair(const void* mask, int mode, size_t off,
                                          bool& m0, bool& m1) {
    if (mode == 1) {
        float2 v = *(const float2*)((const float*)mask + off);
        m0 = v.x != 0.0f; m1 = v.y != 0.0f;
    } else if (mode == 2) {
        int2 v = *(const int2*)((const int*)mask + off);
        m0 = v.x != 0; m1 = v.y != 0;
    } else {
        const unsigned char* p = (const unsigned char*)mask + off;
        m0 = p[0] != 0; m1 = p[1] != 0;
    }
}

// ============================================================================
// Tensor-core fused attention. Per CTA: (bh, 16-query tile), 8 warps.
//  Phase 1: S = QK^T via tf32 mma (K-tiles of 128), mask, e=exp(s) (no max
//           pass; scores bounded), e-strip [16][2048] fp32 in smem, rowsums.
//  Write attn = e * inv(rowsum) (fp32, vectorized).
//  Phase 2: ctx = (e@V) * inv via bf16 mma (V transposed to [d][k] bf16).
// smem ~168 KB -> 1 CTA/SM.
// ============================================================================
#define EP 2064          // e-strip pitch (floats)
#define QP 68            // Q tile pitch
#define KP 68            // K tile pitch (floats) / Vt & Pb word pitch
#define ATT_SMEM_FLOATS (16*EP + 16*QP + 128*KP + 128 + 16)
#define ATT_SMEM_BYTES (ATT_SMEM_FLOATS * 4)

__global__ __launch_bounds__(256) void attn_mma(
        const float* __restrict__ Qp, const float* __restrict__ Kp,
        const float* __restrict__ Vp, const void* __restrict__ mask,
        float* __restrict__ attn_out, float* __restrict__ ctx_out) {
    extern __shared__ float sm[];
    float*        Es  = sm;                       // [16][EP]
    float*        Qs  = Es + 16 * EP;             // [16][QP]
    float*        Un  = Qs + 16 * QP;             // union: Kt [128][KP] fp32
    unsigned int* Vw  = (unsigned int*)Un;        //        Vt [64][KP] bf16x2 words
    unsigned int* Pb  = (unsigned int*)Un + 64 * KP; // Pb [16][KP] bf16x2 words
    float*        rowsumW = Un + 128 * KP;        // [8][16]
    float*        inv = rowsumW + 128;            // [16]

    const int t = threadIdx.x, w = t >> 5, l = t & 31;
    const int g = l >> 2, tg = l & 3;
    const int bh = blockIdx.y, b = bh >> 3, h = bh & 7;
    const int q0 = blockIdx.x * 16;
    const float* Qb = Qp + (size_t)bh * SS * DH;
    const float* Kb = Kp + (size_t)bh * SS * DH;
    const float* Vb = Vp + (size_t)bh * SS * DH;
    const int mode = g_mask_mode;

    // ---- load Q tile ----
    for (int i = t; i < 16 * 64; i += 256) {
        const int r = i >> 6, c = i & 63;
        Qs[r * QP + c] = Qb[(size_t)(q0 + r) * DH + c];
    }
    __syncthreads();

    // ---- Q fragments (tf32), reused for all 16 K-blocks ----
    unsigned int A[8][4];
    #pragma unroll
    for (int ks = 0; ks < 8; ++ks) {
        A[ks][0] = f2tf32(Qs[g * QP + ks * 8 + tg]);
        A[ks][1] = f2tf32(Qs[(g + 8) * QP + ks * 8 + tg]);
        A[ks][2] = f2tf32(Qs[g * QP + ks * 8 + tg + 4]);
        A[ks][3] = f2tf32(Qs[(g + 8) * QP + ks * 8 + tg + 4]);
    }

    const size_t mrow0 = ((size_t)b * SS + q0 + g) * SS;
    const size_t mrow1 = ((size_t)b * SS + q0 + g + 8) * SS;
    float rs0 = 0.0f, rs1 = 0.0f;

    // ================= Phase 1: scores + exp =================
    for (int kb = 0; kb < 16; ++kb) {
        __syncthreads();
        for (int i = t; i < 2048; i += 256) {           // 128 keys x 64 d
            const int key = i >> 4, c4 = (i & 15) << 2;
            float4 v = *(const float4*)(Kb + (size_t)(kb * 128 + key) * DH + c4);
            float* dst = Un + key * KP + c4;
            dst[0] = __uint_as_float(f2tf32(v.x));
            dst[1] = __uint_as_float(f2tf32(v.y));
            dst[2] = __uint_as_float(f2tf32(v.z));
            dst[3] = __uint_as_float(f2tf32(v.w));
        }
        __syncthreads();
        #pragma unroll
        for (int nt = 0; nt < 2; ++nt) {
            float c0 = 0, c1 = 0, c2 = 0, c3 = 0;
            const int krow = (w * 16 + nt * 8 + g) * KP;
            #pragma unroll
            for (int ks = 0; ks < 8; ++ks) {
                const unsigned int b0 = __float_as_uint(Un[krow + ks * 8 + tg]);
                const unsigned int b1 = __float_as_uint(Un[krow + ks * 8 + tg + 4]);
                mma_tf32(c0, c1, c2, c3, A[ks][0], A[ks][1], A[ks][2], A[ks][3], b0, b1);
            }
            const int kcol = kb * 128 + w * 16 + nt * 8 + 2 * tg;
            bool m0, m1, m2, m3;
            mask_pair(mask, mode, mrow0 + kcol, m0, m1);
            mask_pair(mask, mode, mrow1 + kcol, m2, m3);
            const float e0 = m0 ? 0.0f : __expf(c0 * 0.125f);
            const float e1 = m1 ? 0.0f : __expf(c1 * 0.125f);
            const float e2 = m2 ? 0.0f : __expf(c2 * 0.125f);
            const float e3 = m3 ? 0.0f : __expf(c3 * 0.125f);
            *(float2*)(Es + g * EP + kcol)       = make_float2(e0, e1);
            *(float2*)(Es + (g + 8) * EP + kcol) = make_float2(e2, e3);
            rs0 += e0 + e1;
            rs1 += e2 + e3;
        }
    }
    // rowsum reduce over tig lanes, then across warps
    rs0 += __shfl_xor_sync(0xffffffffu, rs0, 1);
    rs0 += __shfl_xor_sync(0xffffffffu, rs0, 2);
    rs1 += __shfl_xor_sync(0xffffffffu, rs1, 1);
    rs1 += __shfl_xor_sync(0xffffffffu, rs1, 2);
    if (tg == 0) {
        rowsumW[w * 16 + g]     = rs0;
        rowsumW[w * 16 + g + 8] = rs1;
    }
    __syncthreads();
    if (t < 16) {
        float s = 0.0f;
        #pragma unroll
        for (int ww = 0; ww < 8; ++ww) s += rowsumW[ww * 16 + t];
        inv[t] = 1.0f / s;
    }
    __syncthreads();

    // ---- write normalized attn (float4) ----
    {
        float* abase = attn_out + ((size_t)bh * SS + q0) * SS;
        for (int i = t; i < 8192; i += 256) {
            const int r = i >> 9, k = (i & 511) << 2;
            float4 v = *(const float4*)(Es + r * EP + k);
            const float iv = inv[r];
            v.x *= iv; v.y *= iv; v.z *= iv; v.w *= iv;
            *(float4*)(abase + (size_t)r * SS + k) = v;
        }
    }

    // ================= Phase 2: ctx = (e @ V) * inv, bf16 mma =================
    float cc0 = 0, cc1 = 0, cc2 = 0, cc3 = 0;
    for (int kb = 0; kb < 16; ++kb) {
        __syncthreads();
        // V chunk -> Vt[d][key] bf16 (transposed, pair-packed along key)
        for (int i = t; i < 4096; i += 256) {           // 64 d x 64 key-pairs
            const int d = i & 63, kp = i >> 6;
            const float f0 = Vb[(size_t)(kb * 128 + 2 * kp) * DH + d];
            const float f1 = Vb[(size_t)(kb * 128 + 2 * kp + 1) * DH + d];
            Vw[d * KP + kp] = pack_bf16(f0, f1);
        }
        // E chunk -> Pb[r][k] bf16 pairs
        for (int i = t; i < 1024; i += 256) {           // 16 r x 64 key-pairs
            const int r = i >> 6, kp = i & 63;
            const float e0 = Es[r * EP + kb * 128 + 2 * kp];
            const float e1 = Es[r * EP + kb * 128 + 2 * kp + 1];
            Pb[r * KP + kp] = pack_bf16(e0, e1);
        }
        __syncthreads();
        const int vrow = (w * 8 + g) * KP;
        #pragma unroll
        for (int ks = 0; ks < 8; ++ks) {
            const unsigned int a0 = Pb[g * KP + ks * 8 + tg];
            const unsigned int a1 = Pb[(g + 8) * KP + ks * 8 + tg];
            const unsigned int a2 = Pb[g * KP + ks * 8 + tg + 4];
            const unsigned int a3 = Pb[(g + 8) * KP + ks * 8 + tg + 4];
            const unsigned int b0 = Vw[vrow + ks * 8 + tg];
            const unsigned int b1 = Vw[vrow + ks * 8 + tg + 4];
            mma_bf16(cc0, cc1, cc2, cc3, a0, a1, a2, a3, b0, b1);
        }
    }
    // write ctx (transposed layout [B,S,H*64]) with normalization
    {
        const int d0 = w * 8 + 2 * tg;
        const float i0 = inv[g], i1 = inv[g + 8];
        float* c0p = ctx_out + ((size_t)b * SS + q0 + g) * DM + h * DH + d0;
        float* c1p = ctx_out + ((size_t)b * SS + q0 + g + 8) * DM + h * DH + d0;
        c0p[0] = cc0 * i0; c0p[1] = cc1 * i0;
        c1p[0] = cc2 * i1; c1p[1] = cc3 * i1;
    }
}

// ============================================================================
// LayerNorm over last dim (512), one block (128 threads) per row
// ============================================================================
__global__ __launch_bounds__(128) void ln512(
        const float* __restrict__ x, const float* __restrict__ gamma,
        const float* __restrict__ beta, float* __restrict__ out) {
    __shared__ float sh[8];
    const int row = blockIdx.x;
    const int t = threadIdx.x;
    const float* xr = x + (size_t)row * DM;
    float4 v = *(const float4*)(xr + t * 4);
    float s  = v.x + v.y + v.z + v.w;
    float s2 = v.x * v.x + v.y * v.y + v.z * v.z + v.w * v.w;
    #pragma unroll
    for (int off = 16; off; off >>= 1) {
        s  += __shfl_xor_sync(0xffffffffu, s,  off);
        s2 += __shfl_xor_sync(0xffffffffu, s2, off);
    }
    if ((t & 31) == 0) { sh[t >> 5] = s; sh[4 + (t >> 5)] = s2; }
    __syncthreads();
    s  = sh[0] + sh[1] + sh[2] + sh[3];
    s2 = sh[4] + sh[5] + sh[6] + sh[7];
    const float mean = s * (1.0f / 512.0f);
    const float var  = s2 * (1.0f / 512.0f) - mean * mean;
    const float r    = rsqrtf(var + 1e-5f);
    float4 gv = *(const float4*)(gamma + t * 4);
    float4 bv = *(const float4*)(beta + t * 4);
    float4 o;
    o.x = (v.x - mean) * r * gv.x + bv.x;
    o.y = (v.y - mean) * r * gv.y + bv.y;
    o.z = (v.z - mean) * r * gv.z + bv.z;
    o.w = (v.w - mean) * r * gv.w + bv.w;
    *(float4*)(out + (size_t)row * DM + t * 4) = o;
}

// ============================================================================
extern "C" void kernel_launch(void* const* d_in, const int* in_sizes, int n_in,
                              void* d_out, int out_size) {
    (void)in_sizes; (void)n_in; (void)out_size;
    const float* input_Q = (const float*)d_in[0];
    const float* input_K = (const float*)d_in[1];
    const float* input_V = (const float*)d_in[2];
    const void*  mask    = d_in[3];
    const float* W_Q     = (const float*)d_in[4];
    const float* W_K     = (const float*)d_in[5];
    // d_in[6] = W_V intentionally unused (reference bug: V projected with W_K)
    const float* W_fc    = (const float*)d_in[7];
    const float* gamma   = (const float*)d_in[8];
    const float* beta    = (const float*)d_in[9];

    float* out      = (float*)d_out;
    float* normed   = out;                          // 4*2048*512 floats
    float* attn_out = out + (size_t)BB * SS * DM;   // 4*8*2048*2048 floats

    float *Qp, *Kp, *Vp, *ctx, *x;
    cudaGetSymbolAddress((void**)&Qp,  g_Qp);
    cudaGetSymbolAddress((void**)&Kp,  g_Kp);
    cudaGetSymbolAddress((void**)&Vp,  g_Vp);
    cudaGetSymbolAddress((void**)&ctx, g_ctx);
    cudaGetSymbolAddress((void**)&x,   g_x);

    detect_mask_mode<<<1, 32>>>((const unsigned int*)mask);

    const dim3 gg(DM / 64, (BB * SS) / 64);   // 8 x 128
    gemm512<<<gg, 256>>>(input_Q, W_Q, nullptr, Qp);
    gemm512<<<gg, 256>>>(input_K, W_K, nullptr, Kp);
    gemm512<<<gg, 256>>>(input_V, W_K, nullptr, Vp);   // W_K, per source bug

    cudaFuncSetAttribute(attn_mma,
                         cudaFuncAttributeMaxDynamicSharedMemorySize, ATT_SMEM_BYTES);
    attn_mma<<<dim3(SS / 16, BB * HH), 256, ATT_SMEM_BYTES>>>(
        Qp, Kp, Vp, mask, attn_out, ctx);

    gemm512<<<gg, 256>>>(ctx, W_fc, input_Q, x);       // fused residual
    ln512<<<BB * SS, 128>>>(x, gamma, beta, normed);
}

// round 5
// speedup vs baseline: 1.7164x; 1.7164x over previous
#include <cuda_runtime.h>
#include <cuda_bf16.h>
#include <cuda_fp16.h>

#define BB 4
#define HH 8
#define SS 2048
#define DM 512
#define DH 64

// ---- scratch (static device allocs: allowed; cudaMalloc is not) ----
__device__ float g_Qp[BB*SS*DM];
__device__ float g_Kp[BB*SS*DM];
__device__ float g_Vp[BB*SS*DM];
__device__ float g_ctx[BB*SS*DM];
__device__ float g_x[BB*SS*DM];
__device__ int   g_mask_mode;   // 0=uint8, 1=float32, 2=int32

// ============================================================================
// Detect on-device dtype of the bool attention_mask (see R2 notes).
// ============================================================================
__global__ void detect_mask_mode(const unsigned int* __restrict__ m) {
    if (threadIdx.x == 0) {
        bool f01 = true, i01 = true;
        for (int i = 0; i < 1024; ++i) {
            const unsigned int w = m[i];
            if (w != 0u && w != 0x3F800000u) f01 = false;
            if (w != 0u && w != 1u)          i01 = false;
        }
        g_mask_mode = f01 ? 1 : (i01 ? 2 : 0);
    }
}

// ============================================================================
// fp32 SIMT GEMM (near fp32 roofline, 157us each — replaced next round)
// ============================================================================
__global__ __launch_bounds__(256) void gemm512(
        const float* __restrict__ A, const float* __restrict__ W,
        const float* __restrict__ resid, float* __restrict__ C) {
    __shared__ float As[64][17];
    __shared__ float Ws[64][17];
    const int m0 = blockIdx.y * 64;
    const int n0 = blockIdx.x * 64;
    const int t  = threadIdx.x;
    const int tx = t & 15, ty = t >> 4;
    const int lrow = t >> 2, lc4 = (t & 3) << 2;
    float acc[4][4] = {};
    for (int k0 = 0; k0 < 512; k0 += 16) {
        float4 av = *(const float4*)(A + (size_t)(m0 + lrow) * 512 + k0 + lc4);
        float4 wv = *(const float4*)(W + (size_t)(n0 + lrow) * 512 + k0 + lc4);
        As[lrow][lc4+0] = av.x; As[lrow][lc4+1] = av.y;
        As[lrow][lc4+2] = av.z; As[lrow][lc4+3] = av.w;
        Ws[lrow][lc4+0] = wv.x; Ws[lrow][lc4+1] = wv.y;
        Ws[lrow][lc4+2] = wv.z; Ws[lrow][lc4+3] = wv.w;
        __syncthreads();
        #pragma unroll
        for (int kk = 0; kk < 16; ++kk) {
            float a[4], bv[4];
            #pragma unroll
            for (int i = 0; i < 4; ++i) a[i] = As[ty + 16*i][kk];
            #pragma unroll
            for (int j = 0; j < 4; ++j) bv[j] = Ws[tx + 16*j][kk];
            #pragma unroll
            for (int i = 0; i < 4; ++i)
                #pragma unroll
                for (int j = 0; j < 4; ++j)
                    acc[i][j] = fmaf(a[i], bv[j], acc[i][j]);
        }
        __syncthreads();
    }
    #pragma unroll
    for (int i = 0; i < 4; ++i) {
        const int m = m0 + ty + 16*i;
        #pragma unroll
        for (int j = 0; j < 4; ++j) {
            const int n = n0 + tx + 16*j;
            float v = acc[i][j];
            if (resid) v += resid[(size_t)m * 512 + n];
            C[(size_t)m * 512 + n] = v;
        }
    }
}

// ---------------------------------------------------------------------------
// mma helpers
// ---------------------------------------------------------------------------
__device__ __forceinline__ unsigned int f2tf32(float x) {
    unsigned int u;
    asm("cvt.rna.tf32.f32 %0, %1;" : "=r"(u) : "f"(x));
    return u;
}
__device__ __forceinline__ unsigned int pack_f16(float lo, float hi) {
    unsigned int u;
    asm("cvt.rn.f16x2.f32 %0, %1, %2;" : "=r"(u) : "f"(hi), "f"(lo));
    return u;
}
__device__ __forceinline__ void mma_tf32(float& c0, float& c1, float& c2, float& c3,
        unsigned int a0, unsigned int a1, unsigned int a2, unsigned int a3,
        unsigned int b0, unsigned int b1) {
    asm volatile(
        "mma.sync.aligned.m16n8k8.row.col.f32.tf32.tf32.f32 "
        "{%0,%1,%2,%3}, {%4,%5,%6,%7}, {%8,%9}, {%0,%1,%2,%3};\n"
        : "+f"(c0), "+f"(c1), "+f"(c2), "+f"(c3)
        : "r"(a0), "r"(a1), "r"(a2), "r"(a3), "r"(b0), "r"(b1));
}
__device__ __forceinline__ void mma_f16(float& c0, float& c1, float& c2, float& c3,
        unsigned int a0, unsigned int a1, unsigned int a2, unsigned int a3,
        unsigned int b0, unsigned int b1) {
    asm volatile(
        "mma.sync.aligned.m16n8k16.row.col.f32.f16.f16.f32 "
        "{%0,%1,%2,%3}, {%4,%5,%6,%7}, {%8,%9}, {%0,%1,%2,%3};\n"
        : "+f"(c0), "+f"(c1), "+f"(c2), "+f"(c3)
        : "r"(a0), "r"(a1), "r"(a2), "r"(a3), "r"(b0), "r"(b1));
}

__device__ __forceinline__ void mask_pair(const void* mask, int mode, size_t off,
                                          bool& m0, bool& m1) {
    if (mode == 1) {
        float2 v = *(const float2*)((const float*)mask + off);
        m0 = v.x != 0.0f; m1 = v.y != 0.0f;
    } else if (mode == 2) {
        int2 v = *(const int2*)((const int*)mask + off);
        m0 = v.x != 0; m1 = v.y != 0;
    } else {
        const unsigned char* p = (const unsigned char*)mask + off;
        m0 = p[0] != 0; m1 = p[1] != 0;
    }
}

// ============================================================================
// Tensor-core fused attention, v2.
// CTA = (bh, 32-query tile), 512 threads (16 warps), 1 CTA/SM (~178KB smem).
// Phase 1: S=QK^T tf32 mma over 16 K-tiles of 128 keys (register-prefetched),
//          e=exp(s*0.125) masked (no max pass; scores bounded), store e-strip
//          [32][2048] fp16, accumulate rowsums.
// Write attn = e * inv(rowsum).
// Phase 2: ctx = (e@V)*inv via f16 mma; A-frags read straight from the strip.
// ============================================================================
#define EPW 1032   // e-strip pitch in half2 words (1024 + 8 pad)
#define KP  68     // K tile pitch (floats)
#define VKP 69     // Vt pitch (half2 words)
#define QP  68     // Q tile pitch (floats)

#define SM_EW    0                         // uint [32*EPW]
#define SM_KT    (32*EPW)                  // float [128*KP] (phase2: Vt uint [64*VKP])
#define SM_QS    (SM_KT + 128*KP)          // float [32*QP]
#define SM_RSUM  (SM_QS + 32*QP)           // float [16*32]
#define SM_INV   (SM_RSUM + 16*32)         // float [32]
#define ATT_WORDS (SM_INV + 32)
#define ATT_SMEM_BYTES (ATT_WORDS * 4)

__global__ __launch_bounds__(512, 1) void attn_mma(
        const float* __restrict__ Qp, const float* __restrict__ Kp,
        const float* __restrict__ Vp, const void* __restrict__ mask,
        float* __restrict__ attn_out, float* __restrict__ ctx_out) {
    extern __shared__ float sm[];
    unsigned int* Ew   = (unsigned int*)sm;            // fp16 e-strip
    float*        Kt   = sm + SM_KT;
    unsigned int* Vtw  = (unsigned int*)(sm + SM_KT);
    float*        Qs   = sm + SM_QS;
    float*        rowsumW = sm + SM_RSUM;
    float*        inv  = sm + SM_INV;

    const int t = threadIdx.x, w = t >> 5, l = t & 31;
    const int g = l >> 2, tg = l & 3;
    const int bh = blockIdx.y, b = bh >> 3, h = bh & 7;
    const int q0 = blockIdx.x * 32;
    const float* Qb = Qp + (size_t)bh * SS * DH;
    const float* Kb = Kp + (size_t)bh * SS * DH;
    const float* Vb = Vp + (size_t)bh * SS * DH;
    const int mode = g_mask_mode;

    // ---- load Q tile [32][64] ----
    for (int i = t; i < 32 * 64; i += 512) {
        const int r = i >> 6, c = i & 63;
        Qs[r * QP + c] = Qb[(size_t)(q0 + r) * DH + c];
    }

    float rs[4] = {0, 0, 0, 0};

    // ================= Phase 1: scores + exp =================
    // K tile: 128 keys x 64 d; per thread 4 float4 (prefetched in regs)
    float4 kreg[4];
    {
        #pragma unroll
        for (int j = 0; j < 4; ++j) {
            const int i = t + j * 512;
            const int key = i >> 4, c4 = (i & 15) << 2;
            kreg[j] = *(const float4*)(Kb + (size_t)key * DH + c4);
        }
    }
    for (int kb = 0; kb < 16; ++kb) {
        __syncthreads();   // prev mma done reading Kt (also covers Qs at kb=0)
        #pragma unroll
        for (int j = 0; j < 4; ++j) {
            const int i = t + j * 512;
            const int key = i >> 4, c4 = (i & 15) << 2;
            float* dst = Kt + key * KP + c4;
            dst[0] = __uint_as_float(f2tf32(kreg[j].x));
            dst[1] = __uint_as_float(f2tf32(kreg[j].y));
            dst[2] = __uint_as_float(f2tf32(kreg[j].z));
            dst[3] = __uint_as_float(f2tf32(kreg[j].w));
        }
        __syncthreads();
        if (kb < 15) {     // prefetch next tile; overlaps with mma below
            #pragma unroll
            for (int j = 0; j < 4; ++j) {
                const int i = t + j * 512;
                const int key = i >> 4, c4 = (i & 15) << 2;
                kreg[j] = *(const float4*)(Kb + (size_t)((kb + 1) * 128 + key) * DH + c4);
            }
        }
        const int krow = (w * 8 + g) * KP;     // warp w owns keys [w*8, w*8+8)
        const int kcol = kb * 128 + w * 8 + 2 * tg;
        #pragma unroll
        for (int mt = 0; mt < 2; ++mt) {
            // A frags for rows mt*16 .. mt*16+15
            unsigned int A2[8][4];
            #pragma unroll
            for (int ks = 0; ks < 8; ++ks) {
                A2[ks][0] = f2tf32(Qs[(mt * 16 + g) * QP + ks * 8 + tg]);
                A2[ks][1] = f2tf32(Qs[(mt * 16 + g + 8) * QP + ks * 8 + tg]);
                A2[ks][2] = f2tf32(Qs[(mt * 16 + g) * QP + ks * 8 + tg + 4]);
                A2[ks][3] = f2tf32(Qs[(mt * 16 + g + 8) * QP + ks * 8 + tg + 4]);
            }
            float c0 = 0, c1 = 0, c2 = 0, c3 = 0;
            #pragma unroll
            for (int ks = 0; ks < 8; ++ks) {
                const unsigned int b0 = __float_as_uint(Kt[krow + ks * 8 + tg]);
                const unsigned int b1 = __float_as_uint(Kt[krow + ks * 8 + tg + 4]);
                mma_tf32(c0, c1, c2, c3, A2[ks][0], A2[ks][1], A2[ks][2], A2[ks][3], b0, b1);
            }
            const int r0 = q0 + mt * 16 + g;
            bool m0, m1, m2, m3;
            mask_pair(mask, mode, ((size_t)b * SS + r0) * SS + kcol, m0, m1);
            mask_pair(mask, mode, ((size_t)b * SS + r0 + 8) * SS + kcol, m2, m3);
            const float e0 = m0 ? 0.0f : __expf(c0 * 0.125f);
            const float e1 = m1 ? 0.0f : __expf(c1 * 0.125f);
            const float e2 = m2 ? 0.0f : __expf(c2 * 0.125f);
            const float e3 = m3 ? 0.0f : __expf(c3 * 0.125f);
            const int wcol = kb * 64 + w * 4 + tg;   // half2-word column
            Ew[(mt * 16 + g) * EPW + wcol]     = pack_f16(e0, e1);
            Ew[(mt * 16 + g + 8) * EPW + wcol] = pack_f16(e2, e3);
            rs[mt * 2]     += e0 + e1;
            rs[mt * 2 + 1] += e2 + e3;
        }
    }
    // ---- rowsum reduce: over tg lanes, then across 16 warps ----
    #pragma unroll
    for (int i = 0; i < 4; ++i) {
        rs[i] += __shfl_xor_sync(0xffffffffu, rs[i], 1);
        rs[i] += __shfl_xor_sync(0xffffffffu, rs[i], 2);
    }
    if (tg == 0) {
        rowsumW[w * 32 + g]      = rs[0];
        rowsumW[w * 32 + g + 8]  = rs[1];
        rowsumW[w * 32 + g + 16] = rs[2];
        rowsumW[w * 32 + g + 24] = rs[3];
    }
    __syncthreads();
    if (t < 32) {
        float s = 0.0f;
        #pragma unroll
        for (int ww = 0; ww < 16; ++ww) s += rowsumW[ww * 32 + t];
        inv[t] = 1.0f / s;
    }
    __syncthreads();

    // ---- write normalized attn from fp16 strip ----
    {
        float* abase = attn_out + ((size_t)bh * SS + q0) * SS;
        for (int i = t; i < 32 * 512; i += 512) {
            const int r = i >> 9, c = i & 511;        // c indexes float4 groups
            const unsigned int w0 = Ew[r * EPW + c * 2];
            const unsigned int w1 = Ew[r * EPW + c * 2 + 1];
            const half2 h0 = *(const half2*)&w0;
            const half2 h1 = *(const half2*)&w1;
            const float iv = inv[r];
            float4 o;
            o.x = __half2float(h0.x) * iv;
            o.y = __half2float(h0.y) * iv;
            o.z = __half2float(h1.x) * iv;
            o.w = __half2float(h1.y) * iv;
            *(float4*)(abase + (size_t)r * SS + c * 4) = o;
        }
    }

    // ================= Phase 2: ctx = (e @ V) * inv, f16 mma =================
    // warps 0-7: rows 0-15 (mt=0); warps 8-15: rows 16-31. d-chunk = (w&7)*8.
    const int mt2 = w >> 3, dbase = (w & 7) * 8;
    float cc0 = 0, cc1 = 0, cc2 = 0, cc3 = 0;
    // per thread 8 (d, key-pair) elements, prefetched in regs
    float vf0[8], vf1[8];
    {
        #pragma unroll
        for (int j = 0; j < 8; ++j) {
            const int i = t + j * 512;
            const int d = i & 63, kp = i >> 6;
            vf0[j] = Vb[(size_t)(2 * kp) * DH + d];
            vf1[j] = Vb[(size_t)(2 * kp + 1) * DH + d];
        }
    }
    for (int kb = 0; kb < 16; ++kb) {
        __syncthreads();   // prev mma done reading Vt / attn-write done at kb=0
        #pragma unroll
        for (int j = 0; j < 8; ++j) {
            const int i = t + j * 512;
            const int d = i & 63, kp = i >> 6;
            Vtw[d * VKP + kp] = pack_f16(vf0[j], vf1[j]);
        }
        __syncthreads();
        if (kb < 15) {
            #pragma unroll
            for (int j = 0; j < 8; ++j) {
                const int i = t + j * 512;
                const int d = i & 63, kp = i >> 6;
                vf0[j] = Vb[(size_t)((kb + 1) * 128 + 2 * kp) * DH + d];
                vf1[j] = Vb[(size_t)((kb + 1) * 128 + 2 * kp + 1) * DH + d];
            }
        }
        const int arow0 = (mt2 * 16 + g) * EPW + kb * 64;
        const int arow1 = (mt2 * 16 + g + 8) * EPW + kb * 64;
        const int vrow  = (dbase + g) * VKP;
        #pragma unroll
        for (int ks = 0; ks < 8; ++ks) {
            const unsigned int a0 = Ew[arow0 + ks * 8 + tg];
            const unsigned int a1 = Ew[arow1 + ks * 8 + tg];
            const unsigned int a2 = Ew[arow0 + ks * 8 + tg + 4];
            const unsigned int a3 = Ew[arow1 + ks * 8 + tg + 4];
            const unsigned int b0 = Vtw[vrow + ks * 8 + tg];
            const unsigned int b1 = Vtw[vrow + ks * 8 + tg + 4];
            mma_f16(cc0, cc1, cc2, cc3, a0, a1, a2, a3, b0, b1);
        }
    }
    // write ctx (transposed layout [B,S,H*64]) with normalization
    {
        const int r0 = mt2 * 16 + g;
        const int d0 = dbase + 2 * tg;
        const float i0 = inv[r0], i1 = inv[r0 + 8];
        float* c0p = ctx_out + ((size_t)b * SS + q0 + r0) * DM + h * DH + d0;
        float* c1p = ctx_out + ((size_t)b * SS + q0 + r0 + 8) * DM + h * DH + d0;
        c0p[0] = cc0 * i0; c0p[1] = cc1 * i0;
        c1p[0] = cc2 * i1; c1p[1] = cc3 * i1;
    }
}

// ============================================================================
// LayerNorm over last dim (512), one block (128 threads) per row
// ============================================================================
__global__ __launch_bounds__(128) void ln512(
        const float* __restrict__ x, const float* __restrict__ gamma,
        const float* __restrict__ beta, float* __restrict__ out) {
    __shared__ float sh[8];
    const int row = blockIdx.x;
    const int t = threadIdx.x;
    const float* xr = x + (size_t)row * DM;
    float4 v = *(const float4*)(xr + t * 4);
    float s  = v.x + v.y + v.z + v.w;
    float s2 = v.x * v.x + v.y * v.y + v.z * v.z + v.w * v.w;
    #pragma unroll
    for (int off = 16; off; off >>= 1) {
        s  += __shfl_xor_sync(0xffffffffu, s,  off);
        s2 += __shfl_xor_sync(0xffffffffu, s2, off);
    }
    if ((t & 31) == 0) { sh[t >> 5] = s; sh[4 + (t >> 5)] = s2; }
    __syncthreads();
    s  = sh[0] + sh[1] + sh[2] + sh[3];
    s2 = sh[4] + sh[5] + sh[6] + sh[7];
    const float mean = s * (1.0f / 512.0f);
    const float var  = s2 * (1.0f / 512.0f) - mean * mean;
    const float r    = rsqrtf(var + 1e-5f);
    float4 gv = *(const float4*)(gamma + t * 4);
    float4 bv = *(const float4*)(beta + t * 4);
    float4 o;
    o.x = (v.x - mean) * r * gv.x + bv.x;
    o.y = (v.y - mean) * r * gv.y + bv.y;
    o.z = (v.z - mean) * r * gv.z + bv.z;
    o.w = (v.w - mean) * r * gv.w + bv.w;
    *(float4*)(out + (size_t)row * DM + t * 4) = o;
}

// ============================================================================
extern "C" void kernel_launch(void* const* d_in, const int* in_sizes, int n_in,
                              void* d_out, int out_size) {
    (void)in_sizes; (void)n_in; (void)out_size;
    const float* input_Q = (const float*)d_in[0];
    const float* input_K = (const float*)d_in[1];
    const float* input_V = (const float*)d_in[2];
    const void*  mask    = d_in[3];
    const float* W_Q     = (const float*)d_in[4];
    const float* W_K     = (const float*)d_in[5];
    // d_in[6] = W_V intentionally unused (reference bug: V projected with W_K)
    const float* W_fc    = (const float*)d_in[7];
    const float* gamma   = (const float*)d_in[8];
    const float* beta    = (const float*)d_in[9];

    float* out      = (float*)d_out;
    float* normed   = out;                          // 4*2048*512 floats
    float* attn_out = out + (size_t)BB * SS * DM;   // 4*8*2048*2048 floats

    float *Qp, *Kp, *Vp, *ctx, *x;
    cudaGetSymbolAddress((void**)&Qp,  g_Qp);
    cudaGetSymbolAddress((void**)&Kp,  g_Kp);
    cudaGetSymbolAddress((void**)&Vp,  g_Vp);
    cudaGetSymbolAddress((void**)&ctx, g_ctx);
    cudaGetSymbolAddress((void**)&x,   g_x);

    detect_mask_mode<<<1, 32>>>((const unsigned int*)mask);

    const dim3 gg(DM / 64, (BB * SS) / 64);   // 8 x 128
    gemm512<<<gg, 256>>>(input_Q, W_Q, nullptr, Qp);
    gemm512<<<gg, 256>>>(input_K, W_K, nullptr, Kp);
    gemm512<<<gg, 256>>>(input_V, W_K, nullptr, Vp);   // W_K, per source bug

    cudaFuncSetAttribute(attn_mma,
                         cudaFuncAttributeMaxDynamicSharedMemorySize, ATT_SMEM_BYTES);
    attn_mma<<<dim3(SS / 32, BB * HH), 512, ATT_SMEM_BYTES>>>(
        Qp, Kp, Vp, mask, attn_out, ctx);

    gemm512<<<gg, 256>>>(ctx, W_fc, input_Q, x);       // fused residual
    ln512<<<BB * SS, 128>>>(x, gamma, beta, normed);
}

// round 8
// speedup vs baseline: 2.3210x; 1.3522x over previous
#include <cuda_runtime.h>
#include <cuda_bf16.h>
#include <cuda_fp16.h>

#define BB 4
#define HH 8
#define SS 2048
#define DM 512
#define DH 64

// ---- scratch (static device allocs: allowed; cudaMalloc is not) ----
__device__ float g_Qp[BB*SS*DM];
__device__ float g_Kp[BB*SS*DM];
__device__ float g_Vp[BB*SS*DM];
__device__ float g_ctx[BB*SS*DM];
__device__ float g_x[BB*SS*DM];
__device__ int   g_mask_mode;   // 0=uint8, 1=float32, 2=int32

__global__ void detect_mask_mode(const unsigned int* __restrict__ m) {
    if (threadIdx.x == 0) {
        bool f01 = true, i01 = true;
        for (int i = 0; i < 1024; ++i) {
            const unsigned int w = m[i];
            if (w != 0u && w != 0x3F800000u) f01 = false;
            if (w != 0u && w != 1u)          i01 = false;
        }
        g_mask_mode = f01 ? 1 : (i01 ? 2 : 0);
    }
}

// ---------------------------------------------------------------------------
// mma helpers
// ---------------------------------------------------------------------------
__device__ __forceinline__ unsigned int f2tf32(float x) {
    unsigned int u;
    asm("cvt.rna.tf32.f32 %0, %1;" : "=r"(u) : "f"(x));
    return u;
}
__device__ __forceinline__ unsigned int pack_f16(float lo, float hi) {
    unsigned int u;
    asm("cvt.rn.f16x2.f32 %0, %1, %2;" : "=r"(u) : "f"(hi), "f"(lo));
    return u;
}
__device__ __forceinline__ void mma_tf32(float& c0, float& c1, float& c2, float& c3,
        unsigned int a0, unsigned int a1, unsigned int a2, unsigned int a3,
        unsigned int b0, unsigned int b1) {
    asm volatile(
        "mma.sync.aligned.m16n8k8.row.col.f32.tf32.tf32.f32 "
        "{%0,%1,%2,%3}, {%4,%5,%6,%7}, {%8,%9}, {%0,%1,%2,%3};\n"
        : "+f"(c0), "+f"(c1), "+f"(c2), "+f"(c3)
        : "r"(a0), "r"(a1), "r"(a2), "r"(a3), "r"(b0), "r"(b1));
}
__device__ __forceinline__ void mma_f16(float& c0, float& c1, float& c2, float& c3,
        unsigned int a0, unsigned int a1, unsigned int a2, unsigned int a3,
        unsigned int b0, unsigned int b1) {
    asm volatile(
        "mma.sync.aligned.m16n8k16.row.col.f32.f16.f16.f32 "
        "{%0,%1,%2,%3}, {%4,%5,%6,%7}, {%8,%9}, {%0,%1,%2,%3};\n"
        : "+f"(c0), "+f"(c1), "+f"(c2), "+f"(c3)
        : "r"(a0), "r"(a1), "r"(a2), "r"(a3), "r"(b0), "r"(b1));
}

// ============================================================================
// tf32 tensor-core GEMM: C[M,512] = A[M,512] @ W[512,512]^T (+resid)
// CTA tile 128M x 64N, 256 threads (8 warps in 4x2), k-chunks of 64,
// register-prefetch pipelining. NP=3: 3xTF32 hi/lo split (~fp32 accuracy)
// for GEMMs whose error feeds the attn output (Q,K projections).
// ============================================================================
#define GPA 68
template<int NP>
__global__ __launch_bounds__(256) void gemm_tf32(
        const float* __restrict__ A, const float* __restrict__ W,
        const float* __restrict__ resid, float* __restrict__ C) {
    extern __shared__ float gsm[];
    float* Ah = gsm;                      // [128][GPA]
    float* Wh = Ah + 128 * GPA;           // [64][GPA]
    float* Al = Wh + 64 * GPA;            // NP==3 only
    float* Wl = Al + 128 * GPA;

    const int t = threadIdx.x, w = t >> 5, l = t & 31;
    const int g = l >> 2, tg = l & 3;
    const int wm = w >> 1, wn = w & 1;
    const int m0 = blockIdx.y * 128, n0 = blockIdx.x * 64;
    const int lrow = t >> 4, lc4 = (t & 15) << 2;

    float acc[2][4][4] = {};

    float4 areg[8], wreg[4];
    #pragma unroll
    for (int j = 0; j < 8; ++j)
        areg[j] = *(const float4*)(A + (size_t)(m0 + lrow + j * 16) * 512 + lc4);
    #pragma unroll
    for (int j = 0; j < 4; ++j)
        wreg[j] = *(const float4*)(W + (size_t)(n0 + lrow + j * 16) * 512 + lc4);

    for (int kc = 0; kc < 8; ++kc) {
        __syncthreads();
        #pragma unroll
        for (int j = 0; j < 8; ++j) {
            float* dh = Ah + (lrow + j * 16) * GPA + lc4;
            const float4 v = areg[j];
            const float hx = __uint_as_float(f2tf32(v.x));
            const float hy = __uint_as_float(f2tf32(v.y));
            const float hz = __uint_as_float(f2tf32(v.z));
            const float hw = __uint_as_float(f2tf32(v.w));
            dh[0] = hx; dh[1] = hy; dh[2] = hz; dh[3] = hw;
            if (NP == 3) {
                float* dl = Al + (lrow + j * 16) * GPA + lc4;
                dl[0] = __uint_as_float(f2tf32(v.x - hx));
                dl[1] = __uint_as_float(f2tf32(v.y - hy));
                dl[2] = __uint_as_float(f2tf32(v.z - hz));
                dl[3] = __uint_as_float(f2tf32(v.w - hw));
            }
        }
        #pragma unroll
        for (int j = 0; j < 4; ++j) {
            float* dh = Wh + (lrow + j * 16) * GPA + lc4;
            const float4 v = wreg[j];
            const float hx = __uint_as_float(f2tf32(v.x));
            const float hy = __uint_as_float(f2tf32(v.y));
            const float hz = __uint_as_float(f2tf32(v.z));
            const float hw = __uint_as_float(f2tf32(v.w));
            dh[0] = hx; dh[1] = hy; dh[2] = hz; dh[3] = hw;
            if (NP == 3) {
                float* dl = Wl + (lrow + j * 16) * GPA + lc4;
                dl[0] = __uint_as_float(f2tf32(v.x - hx));
                dl[1] = __uint_as_float(f2tf32(v.y - hy));
                dl[2] = __uint_as_float(f2tf32(v.z - hz));
                dl[3] = __uint_as_float(f2tf32(v.w - hw));
            }
        }
        __syncthreads();
        if (kc < 7) {
            const int k4 = (kc + 1) * 64 + lc4;
            #pragma unroll
            for (int j = 0; j < 8; ++j)
                areg[j] = *(const float4*)(A + (size_t)(m0 + lrow + j * 16) * 512 + k4);
            #pragma unroll
            for (int j = 0; j < 4; ++j)
                wreg[j] = *(const float4*)(W + (size_t)(n0 + lrow + j * 16) * 512 + k4);
        }
        #pragma unroll
        for (int ks = 0; ks < 8; ++ks) {
            unsigned int ah[2][4], bh[4][2];
            #pragma unroll
            for (int mt = 0; mt < 2; ++mt) {
                const int r = wm * 32 + mt * 16;
                ah[mt][0] = __float_as_uint(Ah[(r + g) * GPA + ks * 8 + tg]);
                ah[mt][1] = __float_as_uint(Ah[(r + g + 8) * GPA + ks * 8 + tg]);
                ah[mt][2] = __float_as_uint(Ah[(r + g) * GPA + ks * 8 + tg + 4]);
                ah[mt][3] = __float_as_uint(Ah[(r + g + 8) * GPA + ks * 8 + tg + 4]);
            }
            #pragma unroll
            for (int nt = 0; nt < 4; ++nt) {
                const int r = wn * 32 + nt * 8 + g;
                bh[nt][0] = __float_as_uint(Wh[r * GPA + ks * 8 + tg]);
                bh[nt][1] = __float_as_uint(Wh[r * GPA + ks * 8 + tg + 4]);
            }
            #pragma unroll
            for (int mt = 0; mt < 2; ++mt)
                #pragma unroll
                for (int nt = 0; nt < 4; ++nt)
                    mma_tf32(acc[mt][nt][0], acc[mt][nt][1], acc[mt][nt][2], acc[mt][nt][3],
                             ah[mt][0], ah[mt][1], ah[mt][2], ah[mt][3],
                             bh[nt][0], bh[nt][1]);
            if (NP == 3) {
                unsigned int bl[4][2];
                #pragma unroll
                for (int nt = 0; nt < 4; ++nt) {
                    const int r = wn * 32 + nt * 8 + g;
                    bl[nt][0] = __float_as_uint(Wl[r * GPA + ks * 8 + tg]);
                    bl[nt][1] = __float_as_uint(Wl[r * GPA + ks * 8 + tg + 4]);
                }
                #pragma unroll
                for (int mt = 0; mt < 2; ++mt)
                    #pragma unroll
                    for (int nt = 0; nt < 4; ++nt)
                        mma_tf32(acc[mt][nt][0], acc[mt][nt][1], acc[mt][nt][2], acc[mt][nt][3],
                                 ah[mt][0], ah[mt][1], ah[mt][2], ah[mt][3],
                                 bl[nt][0], bl[nt][1]);
                unsigned int al[2][4];
                #pragma unroll
                for (int mt = 0; mt < 2; ++mt) {
                    const int r = wm * 32 + mt * 16;
                    al[mt][0] = __float_as_uint(Al[(r + g) * GPA + ks * 8 + tg]);
                    al[mt][1] = __float_as_uint(Al[(r + g + 8) * GPA + ks * 8 + tg]);
                    al[mt][2] = __float_as_uint(Al[(r + g) * GPA + ks * 8 + tg + 4]);
                    al[mt][3] = __float_as_uint(Al[(r + g + 8) * GPA + ks * 8 + tg + 4]);
                }
                #pragma unroll
                for (int mt = 0; mt < 2; ++mt)
                    #pragma unroll
                    for (int nt = 0; nt < 4; ++nt)
                        mma_tf32(acc[mt][nt][0], acc[mt][nt][1], acc[mt][nt][2], acc[mt][nt][3],
                                 al[mt][0], al[mt][1], al[mt][2], al[mt][3],
                                 bh[nt][0], bh[nt][1]);
            }
        }
    }
    // epilogue
    #pragma unroll
    for (int mt = 0; mt < 2; ++mt) {
        const int mA = m0 + wm * 32 + mt * 16 + g;
        const int mB = mA + 8;
        #pragma unroll
        for (int nt = 0; nt < 4; ++nt) {
            const int n = n0 + wn * 32 + nt * 8 + 2 * tg;
            float v0 = acc[mt][nt][0], v1 = acc[mt][nt][1];
            float v2 = acc[mt][nt][2], v3 = acc[mt][nt][3];
            if (resid) {
                const float2 r0 = *(const float2*)(resid + (size_t)mA * 512 + n);
                const float2 r1 = *(const float2*)(resid + (size_t)mB * 512 + n);
                v0 += r0.x; v1 += r0.y; v2 += r1.x; v3 += r1.y;
            }
            *(float2*)(C + (size_t)mA * 512 + n) = make_float2(v0, v1);
            *(float2*)(C + (size_t)mB * 512 + n) = make_float2(v2, v3);
        }
    }
}
#define GEMM_SMEM_1 ((128 + 64) * GPA * 4)
#define GEMM_SMEM_3 (2 * (128 + 64) * GPA * 4)

__device__ __forceinline__ void mask_pair(const void* mask, int mode, size_t off,
                                          bool& m0, bool& m1) {
    if (mode == 1) {
        float2 v = *(const float2*)((const float*)mask + off);
        m0 = v.x != 0.0f; m1 = v.y != 0.0f;
    } else if (mode == 2) {
        int2 v = *(const int2*)((const int*)mask + off);
        m0 = v.x != 0; m1 = v.y != 0;
    } else {
        const unsigned char* p = (const unsigned char*)mask + off;
        m0 = p[0] != 0; m1 = p[1] != 0;
    }
}

// ============================================================================
// Tensor-core fused attention (v2 + hoisted Q fragments).
// ============================================================================
#define EPW 1032
#define KP  68
#define VKP 69
#define QP  68

#define SM_EW    0
#define SM_KT    (32*EPW)
#define SM_QS    (SM_KT + 128*KP)
#define SM_RSUM  (SM_QS + 32*QP)
#define SM_INV   (SM_RSUM + 16*32)
#define ATT_WORDS (SM_INV + 32)
#define ATT_SMEM_BYTES (ATT_WORDS * 4)

__global__ __launch_bounds__(512, 1) void attn_mma(
        const float* __restrict__ Qp, const float* __restrict__ Kp,
        const float* __restrict__ Vp, const void* __restrict__ mask,
        float* __restrict__ attn_out, float* __restrict__ ctx_out) {
    extern __shared__ float sm[];
    unsigned int* Ew   = (unsigned int*)sm;
    float*        Kt   = sm + SM_KT;
    unsigned int* Vtw  = (unsigned int*)(sm + SM_KT);
    float*        Qs   = sm + SM_QS;
    float*        rowsumW = sm + SM_RSUM;
    float*        inv  = sm + SM_INV;

    const int t = threadIdx.x, w = t >> 5, l = t & 31;
    const int g = l >> 2, tg = l & 3;
    const int bh = blockIdx.y, b = bh >> 3, h = bh & 7;
    const int q0 = blockIdx.x * 32;
    const float* Qb = Qp + (size_t)bh * SS * DH;
    const float* Kb = Kp + (size_t)bh * SS * DH;
    const float* Vb = Vp + (size_t)bh * SS * DH;
    const int mode = g_mask_mode;

    for (int i = t; i < 32 * 64; i += 512) {
        const int r = i >> 6, c = i & 63;
        Qs[r * QP + c] = Qb[(size_t)(q0 + r) * DH + c];
    }
    __syncthreads();

    // ---- Q fragments: kb-invariant, hoisted out of the K loop ----
    unsigned int A2[2][8][4];
    #pragma unroll
    for (int mt = 0; mt < 2; ++mt)
        #pragma unroll
        for (int ks = 0; ks < 8; ++ks) {
            A2[mt][ks][0] = f2tf32(Qs[(mt * 16 + g) * QP + ks * 8 + tg]);
            A2[mt][ks][1] = f2tf32(Qs[(mt * 16 + g + 8) * QP + ks * 8 + tg]);
            A2[mt][ks][2] = f2tf32(Qs[(mt * 16 + g) * QP + ks * 8 + tg + 4]);
            A2[mt][ks][3] = f2tf32(Qs[(mt * 16 + g + 8) * QP + ks * 8 + tg + 4]);
        }

    float rs[4] = {0, 0, 0, 0};

    // ================= Phase 1: scores + exp =================
    float4 kreg[4];
    #pragma unroll
    for (int j = 0; j < 4; ++j) {
        const int i = t + j * 512;
        const int key = i >> 4, c4 = (i & 15) << 2;
        kreg[j] = *(const float4*)(Kb + (size_t)key * DH + c4);
    }
    for (int kb = 0; kb < 16; ++kb) {
        __syncthreads();
        #pragma unroll
        for (int j = 0; j < 4; ++j) {
            const int i = t + j * 512;
            const int key = i >> 4, c4 = (i & 15) << 2;
            float* dst = Kt + key * KP + c4;
            dst[0] = __uint_as_float(f2tf32(kreg[j].x));
            dst[1] = __uint_as_float(f2tf32(kreg[j].y));
            dst[2] = __uint_as_float(f2tf32(kreg[j].z));
            dst[3] = __uint_as_float(f2tf32(kreg[j].w));
        }
        __syncthreads();
        if (kb < 15) {
            #pragma unroll
            for (int j = 0; j < 4; ++j) {
                const int i = t + j * 512;
                const int key = i >> 4, c4 = (i & 15) << 2;
                kreg[j] = *(const float4*)(Kb + (size_t)((kb + 1) * 128 + key) * DH + c4);
            }
        }
        const int krow = (w * 8 + g) * KP;
        const int kcol = kb * 128 + w * 8 + 2 * tg;
        #pragma unroll
        for (int mt = 0; mt < 2; ++mt) {
            float c0 = 0, c1 = 0, c2 = 0, c3 = 0;
            #pragma unroll
            for (int ks = 0; ks < 8; ++ks) {
                const unsigned int b0 = __float_as_uint(Kt[krow + ks * 8 + tg]);
                const unsigned int b1 = __float_as_uint(Kt[krow + ks * 8 + tg + 4]);
                mma_tf32(c0, c1, c2, c3,
                         A2[mt][ks][0], A2[mt][ks][1], A2[mt][ks][2], A2[mt][ks][3],
                         b0, b1);
            }
            const int r0 = q0 + mt * 16 + g;
            bool m0, m1, m2, m3;
            mask_pair(mask, mode, ((size_t)b * SS + r0) * SS + kcol, m0, m1);
            mask_pair(mask, mode, ((size_t)b * SS + r0 + 8) * SS + kcol, m2, m3);
            const float e0 = m0 ? 0.0f : __expf(c0 * 0.125f);
            const float e1 = m1 ? 0.0f : __expf(c1 * 0.125f);
            const float e2 = m2 ? 0.0f : __expf(c2 * 0.125f);
            const float e3 = m3 ? 0.0f : __expf(c3 * 0.125f);
            const int wcol = kb * 64 + w * 4 + tg;
            Ew[(mt * 16 + g) * EPW + wcol]     = pack_f16(e0, e1);
            Ew[(mt * 16 + g + 8) * EPW + wcol] = pack_f16(e2, e3);
            rs[mt * 2]     += e0 + e1;
            rs[mt * 2 + 1] += e2 + e3;
        }
    }
    #pragma unroll
    for (int i = 0; i < 4; ++i) {
        rs[i] += __shfl_xor_sync(0xffffffffu, rs[i], 1);
        rs[i] += __shfl_xor_sync(0xffffffffu, rs[i], 2);
    }
    if (tg == 0) {
        rowsumW[w * 32 + g]      = rs[0];
        rowsumW[w * 32 + g + 8]  = rs[1];
        rowsumW[w * 32 + g + 16] = rs[2];
        rowsumW[w * 32 + g + 24] = rs[3];
    }
    __syncthreads();
    if (t < 32) {
        float s = 0.0f;
        #pragma unroll
        for (int ww = 0; ww < 16; ++ww) s += rowsumW[ww * 32 + t];
        inv[t] = 1.0f / s;
    }
    __syncthreads();

    // ---- write normalized attn from fp16 strip ----
    {
        float* abase = attn_out + ((size_t)bh * SS + q0) * SS;
        for (int i = t; i < 32 * 512; i += 512) {
            const int r = i >> 9, c = i & 511;
            const unsigned int w0 = Ew[r * EPW + c * 2];
            const unsigned int w1 = Ew[r * EPW + c * 2 + 1];
            const half2 h0 = *(const half2*)&w0;
            const half2 h1 = *(const half2*)&w1;
            const float iv = inv[r];
            float4 o;
            o.x = __half2float(h0.x) * iv;
            o.y = __half2float(h0.y) * iv;
            o.z = __half2float(h1.x) * iv;
            o.w = __half2float(h1.y) * iv;
            *(float4*)(abase + (size_t)r * SS + c * 4) = o;
        }
    }

    // ================= Phase 2: ctx = (e @ V) * inv, f16 mma =================
    const int mt2 = w >> 3, dbase = (w & 7) * 8;
    float cc0 = 0, cc1 = 0, cc2 = 0, cc3 = 0;
    float vf0[8], vf1[8];
    #pragma unroll
    for (int j = 0; j < 8; ++j) {
        const int i = t + j * 512;
        const int d = i & 63, kp = i >> 6;
        vf0[j] = Vb[(size_t)(2 * kp) * DH + d];
        vf1[j] = Vb[(size_t)(2 * kp + 1) * DH + d];
    }
    for (int kb = 0; kb < 16; ++kb) {
        __syncthreads();
        #pragma unroll
        for (int j = 0; j < 8; ++j) {
            const int i = t + j * 512;
            const int d = i & 63, kp = i >> 6;
            Vtw[d * VKP + kp] = pack_f16(vf0[j], vf1[j]);
        }
        __syncthreads();
        if (kb < 15) {
            #pragma unroll
            for (int j = 0; j < 8; ++j) {
                const int i = t + j * 512;
                const int d = i & 63, kp = i >> 6;
                vf0[j] = Vb[(size_t)((kb + 1) * 128 + 2 * kp) * DH + d];
                vf1[j] = Vb[(size_t)((kb + 1) * 128 + 2 * kp + 1) * DH + d];
            }
        }
        const int arow0 = (mt2 * 16 + g) * EPW + kb * 64;
        const int arow1 = (mt2 * 16 + g + 8) * EPW + kb * 64;
        const int vrow  = (dbase + g) * VKP;
        #pragma unroll
        for (int ks = 0; ks < 8; ++ks) {
            const unsigned int a0 = Ew[arow0 + ks * 8 + tg];
            const unsigned int a1 = Ew[arow1 + ks * 8 + tg];
            const unsigned int a2 = Ew[arow0 + ks * 8 + tg + 4];
            const unsigned int a3 = Ew[arow1 + ks * 8 + tg + 4];
            const unsigned int b0 = Vtw[vrow + ks * 8 + tg];
            const unsigned int b1 = Vtw[vrow + ks * 8 + tg + 4];
            mma_f16(cc0, cc1, cc2, cc3, a0, a1, a2, a3, b0, b1);
        }
    }
    {
        const int r0 = mt2 * 16 + g;
        const int d0 = dbase + 2 * tg;
        const float i0 = inv[r0], i1 = inv[r0 + 8];
        float* c0p = ctx_out + ((size_t)b * SS + q0 + r0) * DM + h * DH + d0;
        float* c1p = ctx_out + ((size_t)b * SS + q0 + r0 + 8) * DM + h * DH + d0;
        c0p[0] = cc0 * i0; c0p[1] = cc1 * i0;
        c1p[0] = cc2 * i1; c1p[1] = cc3 * i1;
    }
}

// ============================================================================
// LayerNorm over last dim (512), one block (128 threads) per row
// ============================================================================
__global__ __launch_bounds__(128) void ln512(
        const float* __restrict__ x, const float* __restrict__ gamma,
        const float* __restrict__ beta, float* __restrict__ out) {
    __shared__ float sh[8];
    const int row = blockIdx.x;
    const int t = threadIdx.x;
    const float* xr = x + (size_t)row * DM;
    float4 v = *(const float4*)(xr + t * 4);
    float s  = v.x + v.y + v.z + v.w;
    float s2 = v.x * v.x + v.y * v.y + v.z * v.z + v.w * v.w;
    #pragma unroll
    for (int off = 16; off; off >>= 1) {
        s  += __shfl_xor_sync(0xffffffffu, s,  off);
        s2 += __shfl_xor_sync(0xffffffffu, s2, off);
    }
    if ((t & 31) == 0) { sh[t >> 5] = s; sh[4 + (t >> 5)] = s2; }
    __syncthreads();
    s  = sh[0] + sh[1] + sh[2] + sh[3];
    s2 = sh[4] + sh[5] + sh[6] + sh[7];
    const float mean = s * (1.0f / 512.0f);
    const float var  = s2 * (1.0f / 512.0f) - mean * mean;
    const float r    = rsqrtf(var + 1e-5f);
    float4 gv = *(const float4*)(gamma + t * 4);
    float4 bv = *(const float4*)(beta + t * 4);
    float4 o;
    o.x = (v.x - mean) * r * gv.x + bv.x;
    o.y = (v.y - mean) * r * gv.y + bv.y;
    o.z = (v.z - mean) * r * gv.z + bv.z;
    o.w = (v.w - mean) * r * gv.w + bv.w;
    *(float4*)(out + (size_t)row * DM + t * 4) = o;
}

// ============================================================================
extern "C" void kernel_launch(void* const* d_in, const int* in_sizes, int n_in,
                              void* d_out, int out_size) {
    (void)in_sizes; (void)n_in; (void)out_size;
    const float* input_Q = (const float*)d_in[0];
    const float* input_K = (const float*)d_in[1];
    const float* input_V = (const float*)d_in[2];
    const void*  mask    = d_in[3];
    const float* W_Q     = (const float*)d_in[4];
    const float* W_K     = (const float*)d_in[5];
    // d_in[6] = W_V intentionally unused (reference bug: V projected with W_K)
    const float* W_fc    = (const float*)d_in[7];
    const float* gamma   = (const float*)d_in[8];
    const float* beta    = (const float*)d_in[9];

    float* out      = (float*)d_out;
    float* normed   = out;
    float* attn_out = out + (size_t)BB * SS * DM;

    float *Qp, *Kp, *Vp, *ctx, *x;
    cudaGetSymbolAddress((void**)&Qp,  g_Qp);
    cudaGetSymbolAddress((void**)&Kp,  g_Kp);
    cudaGetSymbolAddress((void**)&Vp,  g_Vp);
    cudaGetSymbolAddress((void**)&ctx, g_ctx);
    cudaGetSymbolAddress((void**)&x,   g_x);

    detect_mask_mode<<<1, 32>>>((const unsigned int*)mask);

    cudaFuncSetAttribute(gemm_tf32<3>,
                         cudaFuncAttributeMaxDynamicSharedMemorySize, GEMM_SMEM_3);
    cudaFuncSetAttribute(gemm_tf32<1>,
                         cudaFuncAttributeMaxDynamicSharedMemorySize, GEMM_SMEM_1);

    const dim3 gg(DM / 64, (BB * SS) / 128);   // 8 x 64
    // Q,K: 3xTF32 (error feeds attn); V,fc: single-pass tf32 (attenuated)
    gemm_tf32<3><<<gg, 256, GEMM_SMEM_3>>>(input_Q, W_Q, nullptr, Qp);
    gemm_tf32<3><<<gg, 256, GEMM_SMEM_3>>>(input_K, W_K, nullptr, Kp);
    gemm_tf32<1><<<gg, 256, GEMM_SMEM_1>>>(input_V, W_K, nullptr, Vp);  // W_K bug

    cudaFuncSetAttribute(attn_mma,
                         cudaFuncAttributeMaxDynamicSharedMemorySize, ATT_SMEM_BYTES);
    attn_mma<<<dim3(SS / 32, BB * HH), 512, ATT_SMEM_BYTES>>>(
        Qp, Kp, Vp, mask, attn_out, ctx);

    gemm_tf32<1><<<gg, 256, GEMM_SMEM_1>>>(ctx, W_fc, input_Q, x);  // fused residual
    ln512<<<BB * SS, 128>>>(x, gamma, beta, normed);
}

// round 14
// speedup vs baseline: 2.8476x; 1.2269x over previous
#include <cuda_runtime.h>
#include <cuda_bf16.h>
#include <cuda_fp16.h>

#define BB 4
#define HH 8
#define SS 2048
#define DM 512
#define DH 64

// ---- scratch (static device allocs: allowed; cudaMalloc is not) ----
__device__ float g_Qp[BB*SS*DM];
__device__ float g_Kp[BB*SS*DM];
__device__ float g_Vp[BB*SS*DM];
__device__ float g_ctx[BB*SS*DM];
__device__ float g_x[BB*SS*DM];
__device__ int   g_mask_mode;   // 0=uint8, 1=float32, 2=int32

__global__ void detect_mask_mode(const unsigned int* __restrict__ m) {
    if (threadIdx.x == 0) {
        bool f01 = true, i01 = true;
        for (int i = 0; i < 1024; ++i) {
            const unsigned int w = m[i];
            if (w != 0u && w != 0x3F800000u) f01 = false;
            if (w != 0u && w != 1u)          i01 = false;
        }
        g_mask_mode = f01 ? 1 : (i01 ? 2 : 0);
    }
}

// ---------------------------------------------------------------------------
// mma helpers
// ---------------------------------------------------------------------------
__device__ __forceinline__ unsigned int f2tf32(float x) {
    unsigned int u;
    asm("cvt.rna.tf32.f32 %0, %1;" : "=r"(u) : "f"(x));
    return u;
}
__device__ __forceinline__ unsigned int pack_f16(float lo, float hi) {
    unsigned int u;
    asm("cvt.rn.f16x2.f32 %0, %1, %2;" : "=r"(u) : "f"(hi), "f"(lo));
    return u;
}
__device__ __forceinline__ void mma_tf32(float& c0, float& c1, float& c2, float& c3,
        unsigned int a0, unsigned int a1, unsigned int a2, unsigned int a3,
        unsigned int b0, unsigned int b1) {
    asm volatile(
        "mma.sync.aligned.m16n8k8.row.col.f32.tf32.tf32.f32 "
        "{%0,%1,%2,%3}, {%4,%5,%6,%7}, {%8,%9}, {%0,%1,%2,%3};\n"
        : "+f"(c0), "+f"(c1), "+f"(c2), "+f"(c3)
        : "r"(a0), "r"(a1), "r"(a2), "r"(a3), "r"(b0), "r"(b1));
}
__device__ __forceinline__ void mma_f16(float& c0, float& c1, float& c2, float& c3,
        unsigned int a0, unsigned int a1, unsigned int a2, unsigned int a3,
        unsigned int b0, unsigned int b1) {
    asm volatile(
        "mma.sync.aligned.m16n8k16.row.col.f32.f16.f16.f32 "
        "{%0,%1,%2,%3}, {%4,%5,%6,%7}, {%8,%9}, {%0,%1,%2,%3};\n"
        : "+f"(c0), "+f"(c1), "+f"(c2), "+f"(c3)
        : "r"(a0), "r"(a1), "r"(a2), "r"(a3), "r"(b0), "r"(b1));
}

// ============================================================================
// tf32 tensor-core GEMM: C[M,512] = A[M,512] @ W[512,512]^T (+resid)
// (unchanged from R8: 45us NP1 / ~90us NP3)
// ============================================================================
#define GPA 68
template<int NP>
__global__ __launch_bounds__(256) void gemm_tf32(
        const float* __restrict__ A, const float* __restrict__ W,
        const float* __restrict__ resid, float* __restrict__ C) {
    extern __shared__ float gsm[];
    float* Ah = gsm;                      // [128][GPA]
    float* Wh = Ah + 128 * GPA;           // [64][GPA]
    float* Al = Wh + 64 * GPA;            // NP==3 only
    float* Wl = Al + 128 * GPA;

    const int t = threadIdx.x, w = t >> 5, l = t & 31;
    const int g = l >> 2, tg = l & 3;
    const int wm = w >> 1, wn = w & 1;
    const int m0 = blockIdx.y * 128, n0 = blockIdx.x * 64;
    const int lrow = t >> 4, lc4 = (t & 15) << 2;

    float acc[2][4][4] = {};

    float4 areg[8], wreg[4];
    #pragma unroll
    for (int j = 0; j < 8; ++j)
        areg[j] = *(const float4*)(A + (size_t)(m0 + lrow + j * 16) * 512 + lc4);
    #pragma unroll
    for (int j = 0; j < 4; ++j)
        wreg[j] = *(const float4*)(W + (size_t)(n0 + lrow + j * 16) * 512 + lc4);

    for (int kc = 0; kc < 8; ++kc) {
        __syncthreads();
        #pragma unroll
        for (int j = 0; j < 8; ++j) {
            float* dh = Ah + (lrow + j * 16) * GPA + lc4;
            const float4 v = areg[j];
            const float hx = __uint_as_float(f2tf32(v.x));
            const float hy = __uint_as_float(f2tf32(v.y));
            const float hz = __uint_as_float(f2tf32(v.z));
            const float hw = __uint_as_float(f2tf32(v.w));
            dh[0] = hx; dh[1] = hy; dh[2] = hz; dh[3] = hw;
            if (NP == 3) {
                float* dl = Al + (lrow + j * 16) * GPA + lc4;
                dl[0] = __uint_as_float(f2tf32(v.x - hx));
                dl[1] = __uint_as_float(f2tf32(v.y - hy));
                dl[2] = __uint_as_float(f2tf32(v.z - hz));
                dl[3] = __uint_as_float(f2tf32(v.w - hw));
            }
        }
        #pragma unroll
        for (int j = 0; j < 4; ++j) {
            float* dh = Wh + (lrow + j * 16) * GPA + lc4;
            const float4 v = wreg[j];
            const float hx = __uint_as_float(f2tf32(v.x));
            const float hy = __uint_as_float(f2tf32(v.y));
            const float hz = __uint_as_float(f2tf32(v.z));
            const float hw = __uint_as_float(f2tf32(v.w));
            dh[0] = hx; dh[1] = hy; dh[2] = hz; dh[3] = hw;
            if (NP == 3) {
                float* dl = Wl + (lrow + j * 16) * GPA + lc4;
                dl[0] = __uint_as_float(f2tf32(v.x - hx));
                dl[1] = __uint_as_float(f2tf32(v.y - hy));
                dl[2] = __uint_as_float(f2tf32(v.z - hz));
                dl[3] = __uint_as_float(f2tf32(v.w - hw));
            }
        }
        __syncthreads();
        if (kc < 7) {
            const int k4 = (kc + 1) * 64 + lc4;
            #pragma unroll
            for (int j = 0; j < 8; ++j)
                areg[j] = *(const float4*)(A + (size_t)(m0 + lrow + j * 16) * 512 + k4);
            #pragma unroll
            for (int j = 0; j < 4; ++j)
                wreg[j] = *(const float4*)(W + (size_t)(n0 + lrow + j * 16) * 512 + k4);
        }
        #pragma unroll
        for (int ks = 0; ks < 8; ++ks) {
            unsigned int ah[2][4], bh[4][2];
            #pragma unroll
            for (int mt = 0; mt < 2; ++mt) {
                const int r = wm * 32 + mt * 16;
                ah[mt][0] = __float_as_uint(Ah[(r + g) * GPA + ks * 8 + tg]);
                ah[mt][1] = __float_as_uint(Ah[(r + g + 8) * GPA + ks * 8 + tg]);
                ah[mt][2] = __float_as_uint(Ah[(r + g) * GPA + ks * 8 + tg + 4]);
                ah[mt][3] = __float_as_uint(Ah[(r + g + 8) * GPA + ks * 8 + tg + 4]);
            }
            #pragma unroll
            for (int nt = 0; nt < 4; ++nt) {
                const int r = wn * 32 + nt * 8 + g;
                bh[nt][0] = __float_as_uint(Wh[r * GPA + ks * 8 + tg]);
                bh[nt][1] = __float_as_uint(Wh[r * GPA + ks * 8 + tg + 4]);
            }
            #pragma unroll
            for (int mt = 0; mt < 2; ++mt)
                #pragma unroll
                for (int nt = 0; nt < 4; ++nt)
                    mma_tf32(acc[mt][nt][0], acc[mt][nt][1], acc[mt][nt][2], acc[mt][nt][3],
                             ah[mt][0], ah[mt][1], ah[mt][2], ah[mt][3],
                             bh[nt][0], bh[nt][1]);
            if (NP == 3) {
                unsigned int bl[4][2];
                #pragma unroll
                for (int nt = 0; nt < 4; ++nt) {
                    const int r = wn * 32 + nt * 8 + g;
                    bl[nt][0] = __float_as_uint(Wl[r * GPA + ks * 8 + tg]);
                    bl[nt][1] = __float_as_uint(Wl[r * GPA + ks * 8 + tg + 4]);
                }
                #pragma unroll
                for (int mt = 0; mt < 2; ++mt)
                    #pragma unroll
                    for (int nt = 0; nt < 4; ++nt)
                        mma_tf32(acc[mt][nt][0], acc[mt][nt][1], acc[mt][nt][2], acc[mt][nt][3],
                                 ah[mt][0], ah[mt][1], ah[mt][2], ah[mt][3],
                                 bl[nt][0], bl[nt][1]);
                unsigned int al[2][4];
                #pragma unroll
                for (int mt = 0; mt < 2; ++mt) {
                    const int r = wm * 32 + mt * 16;
                    al[mt][0] = __float_as_uint(Al[(r + g) * GPA + ks * 8 + tg]);
                    al[mt][1] = __float_as_uint(Al[(r + g + 8) * GPA + ks * 8 + tg]);
                    al[mt][2] = __float_as_uint(Al[(r + g) * GPA + ks * 8 + tg + 4]);
                    al[mt][3] = __float_as_uint(Al[(r + g + 8) * GPA + ks * 8 + tg + 4]);
                }
                #pragma unroll
                for (int mt = 0; mt < 2; ++mt)
                    #pragma unroll
                    for (int nt = 0; nt < 4; ++nt)
                        mma_tf32(acc[mt][nt][0], acc[mt][nt][1], acc[mt][nt][2], acc[mt][nt][3],
                                 al[mt][0], al[mt][1], al[mt][2], al[mt][3],
                                 bh[nt][0], bh[nt][1]);
            }
        }
    }
    // epilogue
    #pragma unroll
    for (int mt = 0; mt < 2; ++mt) {
        const int mA = m0 + wm * 32 + mt * 16 + g;
        const int mB = mA + 8;
        #pragma unroll
        for (int nt = 0; nt < 4; ++nt) {
            const int n = n0 + wn * 32 + nt * 8 + 2 * tg;
            float v0 = acc[mt][nt][0], v1 = acc[mt][nt][1];
            float v2 = acc[mt][nt][2], v3 = acc[mt][nt][3];
            if (resid) {
                const float2 r0 = *(const float2*)(resid + (size_t)mA * 512 + n);
                const float2 r1 = *(const float2*)(resid + (size_t)mB * 512 + n);
                v0 += r0.x; v1 += r0.y; v2 += r1.x; v3 += r1.y;
            }
            *(float2*)(C + (size_t)mA * 512 + n) = make_float2(v0, v1);
            *(float2*)(C + (size_t)mB * 512 + n) = make_float2(v2, v3);
        }
    }
}
#define GEMM_SMEM_1 ((128 + 64) * GPA * 4)
#define GEMM_SMEM_3 (2 * (128 + 64) * GPA * 4)

__device__ __forceinline__ void mask_pair(const void* mask, int mode, size_t off,
                                          bool& m0, bool& m1) {
    if (mode == 1) {
        float2 v = *(const float2*)((const float*)mask + off);
        m0 = v.x != 0.0f; m1 = v.y != 0.0f;
    } else if (mode == 2) {
        int2 v = *(const int2*)((const int*)mask + off);
        m0 = v.x != 0; m1 = v.y != 0;
    } else {
        const unsigned char* p = (const unsigned char*)mask + off;
        m0 = p[0] != 0; m1 = p[1] != 0;
    }
}

// ============================================================================
// Tensor-core fused attention v3: double-buffered K/V tiles, ONE barrier per
// iteration (reads buf[kb&1], stores buf[(kb+1)&1]; end-of-iter sync proves
// all reads of the store target finished two iterations ago). Mask LDGs
// hoisted to iteration start; attn strip write distributed into phase 2.
// smem ~213KB -> 1 CTA/SM, 512 threads.
// ============================================================================
#define EPW 1032   // e-strip pitch (half2 words)
#define KP  68     // K tile pitch (floats)
#define VKP 69     // Vt pitch (half2 words)
#define QP  68     // Q tile pitch (floats)
#define KBUF (128*KP)   // per-buffer stride (words); Vt (64*VKP=4416) fits too

#define SM_EW    0
#define SM_KT    (32*EPW)
#define SM_QS    (SM_KT + 2*KBUF)
#define SM_RSUM  (SM_QS + 32*QP)
#define SM_INV   (SM_RSUM + 16*32)
#define ATT_WORDS (SM_INV + 32)
#define ATT_SMEM_BYTES (ATT_WORDS * 4)

__global__ __launch_bounds__(512, 1) void attn_mma(
        const float* __restrict__ Qp, const float* __restrict__ Kp,
        const float* __restrict__ Vp, const void* __restrict__ mask,
        float* __restrict__ attn_out, float* __restrict__ ctx_out) {
    extern __shared__ float sm[];
    unsigned int* Ew   = (unsigned int*)sm;
    float*        Kt   = sm + SM_KT;                   // 2 x [128][KP]
    unsigned int* Vtw  = (unsigned int*)(sm + SM_KT);  // 2 x [64][VKP]
    float*        Qs   = sm + SM_QS;
    float*        rowsumW = sm + SM_RSUM;
    float*        inv  = sm + SM_INV;

    const int t = threadIdx.x, w = t >> 5, l = t & 31;
    const int g = l >> 2, tg = l & 3;
    const int bh = blockIdx.y, b = bh >> 3, h = bh & 7;
    const int q0 = blockIdx.x * 32;
    const float* Qb = Qp + (size_t)bh * SS * DH;
    const float* Kb = Kp + (size_t)bh * SS * DH;
    const float* Vb = Vp + (size_t)bh * SS * DH;
    const int mode = g_mask_mode;

    for (int i = t; i < 32 * 64; i += 512) {
        const int r = i >> 6, c = i & 63;
        Qs[r * QP + c] = Qb[(size_t)(q0 + r) * DH + c];
    }
    __syncthreads();

    // ---- Q fragments: kb-invariant ----
    unsigned int A2[2][8][4];
    #pragma unroll
    for (int mt = 0; mt < 2; ++mt)
        #pragma unroll
        for (int ks = 0; ks < 8; ++ks) {
            A2[mt][ks][0] = f2tf32(Qs[(mt * 16 + g) * QP + ks * 8 + tg]);
            A2[mt][ks][1] = f2tf32(Qs[(mt * 16 + g + 8) * QP + ks * 8 + tg]);
            A2[mt][ks][2] = f2tf32(Qs[(mt * 16 + g) * QP + ks * 8 + tg + 4]);
            A2[mt][ks][3] = f2tf32(Qs[(mt * 16 + g + 8) * QP + ks * 8 + tg + 4]);
        }

    float rs[4] = {0, 0, 0, 0};
    const int lkey = t >> 4, lc4 = (t & 15) << 2;   // K-tile load coords

    // ================= Phase 1: scores + exp (double-buffered Kt) ===========
    float4 kreg[4];
    #pragma unroll
    for (int j = 0; j < 4; ++j)
        kreg[j] = *(const float4*)(Kb + (size_t)(lkey + j * 32) * DH + lc4);
    #pragma unroll
    for (int j = 0; j < 4; ++j) {
        float* dst = Kt + (lkey + j * 32) * KP + lc4;
        dst[0] = __uint_as_float(f2tf32(kreg[j].x));
        dst[1] = __uint_as_float(f2tf32(kreg[j].y));
        dst[2] = __uint_as_float(f2tf32(kreg[j].z));
        dst[3] = __uint_as_float(f2tf32(kreg[j].w));
    }
    __syncthreads();

    for (int kb = 0; kb < 16; ++kb) {
        const float* cur = Kt + (kb & 1) * KBUF;
        float*       nxt = Kt + ((kb + 1) & 1) * KBUF;
        if (kb < 15) {
            #pragma unroll
            for (int j = 0; j < 4; ++j)
                kreg[j] = *(const float4*)(Kb + (size_t)((kb + 1) * 128 + lkey + j * 32) * DH + lc4);
        }
        // hoisted mask loads (latency hidden under mma)
        const int kcol = kb * 128 + w * 8 + 2 * tg;
        bool mm[2][4];
        #pragma unroll
        for (int mt = 0; mt < 2; ++mt) {
            const int r0 = q0 + mt * 16 + g;
            mask_pair(mask, mode, ((size_t)b * SS + r0) * SS + kcol, mm[mt][0], mm[mt][1]);
            mask_pair(mask, mode, ((size_t)b * SS + r0 + 8) * SS + kcol, mm[mt][2], mm[mt][3]);
        }
        const int krow = (w * 8 + g) * KP;
        #pragma unroll
        for (int mt = 0; mt < 2; ++mt) {
            float c0 = 0, c1 = 0, c2 = 0, c3 = 0;
            #pragma unroll
            for (int ks = 0; ks < 8; ++ks) {
                const unsigned int b0 = __float_as_uint(cur[krow + ks * 8 + tg]);
                const unsigned int b1 = __float_as_uint(cur[krow + ks * 8 + tg + 4]);
                mma_tf32(c0, c1, c2, c3,
                         A2[mt][ks][0], A2[mt][ks][1], A2[mt][ks][2], A2[mt][ks][3],
                         b0, b1);
            }
            const float e0 = mm[mt][0] ? 0.0f : __expf(c0 * 0.125f);
            const float e1 = mm[mt][1] ? 0.0f : __expf(c1 * 0.125f);
            const float e2 = mm[mt][2] ? 0.0f : __expf(c2 * 0.125f);
            const float e3 = mm[mt][3] ? 0.0f : __expf(c3 * 0.125f);
            const int wcol = kb * 64 + w * 4 + tg;
            Ew[(mt * 16 + g) * EPW + wcol]     = pack_f16(e0, e1);
            Ew[(mt * 16 + g + 8) * EPW + wcol] = pack_f16(e2, e3);
            rs[mt * 2]     += e0 + e1;
            rs[mt * 2 + 1] += e2 + e3;
        }
        if (kb < 15) {
            #pragma unroll
            for (int j = 0; j < 4; ++j) {
                float* dst = nxt + (lkey + j * 32) * KP + lc4;
                dst[0] = __uint_as_float(f2tf32(kreg[j].x));
                dst[1] = __uint_as_float(f2tf32(kreg[j].y));
                dst[2] = __uint_as_float(f2tf32(kreg[j].z));
                dst[3] = __uint_as_float(f2tf32(kreg[j].w));
            }
        }
        __syncthreads();
    }

    // ---- rowsum reduce ----
    #pragma unroll
    for (int i = 0; i < 4; ++i) {
        rs[i] += __shfl_xor_sync(0xffffffffu, rs[i], 1);
        rs[i] += __shfl_xor_sync(0xffffffffu, rs[i], 2);
    }
    if (tg == 0) {
        rowsumW[w * 32 + g]      = rs[0];
        rowsumW[w * 32 + g + 8]  = rs[1];
        rowsumW[w * 32 + g + 16] = rs[2];
        rowsumW[w * 32 + g + 24] = rs[3];
    }
    // issue first V-tile loads early (latency hidden under inv computation)
    float vf0[8], vf1[8];
    #pragma unroll
    for (int j = 0; j < 8; ++j) {
        const int i = t + j * 512;
        const int d = i & 63, kp = i >> 6;
        vf0[j] = Vb[(size_t)(2 * kp) * DH + d];
        vf1[j] = Vb[(size_t)(2 * kp + 1) * DH + d];
    }
    __syncthreads();
    if (t < 32) {
        float s = 0.0f;
        #pragma unroll
        for (int ww = 0; ww < 16; ++ww) s += rowsumW[ww * 32 + t];
        inv[t] = 1.0f / s;
    }
    __syncthreads();

    // ================= Phase 2: ctx = (e @ V) * inv (double-buffered Vt) ====
    // attn strip written per-tile inside the loop, overlapping the mma.
    #pragma unroll
    for (int j = 0; j < 8; ++j) {
        const int i = t + j * 512;
        const int d = i & 63, kp = i >> 6;
        Vtw[d * VKP + kp] = pack_f16(vf0[j], vf1[j]);
    }
    __syncthreads();

    const int mt2 = w >> 3, dbase = (w & 7) * 8;
    float cc0 = 0, cc1 = 0, cc2 = 0, cc3 = 0;
    float* abase = attn_out + ((size_t)bh * SS + q0) * SS;

    for (int kb = 0; kb < 16; ++kb) {
        const unsigned int* vcur = Vtw + (kb & 1) * KBUF;
        unsigned int*       vnxt = Vtw + ((kb + 1) & 1) * KBUF;
        if (kb < 15) {
            #pragma unroll
            for (int j = 0; j < 8; ++j) {
                const int i = t + j * 512;
                const int d = i & 63, kp = i >> 6;
                vf0[j] = Vb[(size_t)((kb + 1) * 128 + 2 * kp) * DH + d];
                vf1[j] = Vb[(size_t)((kb + 1) * 128 + 2 * kp + 1) * DH + d];
            }
        }
        // attn write for this tile (2 float4 per thread), overlaps mma below
        #pragma unroll
        for (int j = 0; j < 2; ++j) {
            const int idx = t + j * 512;
            const int r = idx >> 5, c = idx & 31;
            const unsigned int w0 = Ew[r * EPW + kb * 64 + c * 2];
            const unsigned int w1 = Ew[r * EPW + kb * 64 + c * 2 + 1];
            const half2 h0 = *(const half2*)&w0;
            const half2 h1 = *(const half2*)&w1;
            const float iv = inv[r];
            float4 o;
            o.x = __half2float(h0.x) * iv;
            o.y = __half2float(h0.y) * iv;
            o.z = __half2float(h1.x) * iv;
            o.w = __half2float(h1.y) * iv;
            *(float4*)(abase + (size_t)r * SS + kb * 128 + c * 4) = o;
        }
        const int arow0 = (mt2 * 16 + g) * EPW + kb * 64;
        const int arow1 = (mt2 * 16 + g + 8) * EPW + kb * 64;
        const int vrow  = (dbase + g) * VKP;
        #pragma unroll
        for (int ks = 0; ks < 8; ++ks) {
            const unsigned int a0 = Ew[arow0 + ks * 8 + tg];
            const unsigned int a1 = Ew[arow1 + ks * 8 + tg];
            const unsigned int a2 = Ew[arow0 + ks * 8 + tg + 4];
            const unsigned int a3 = Ew[arow1 + ks * 8 + tg + 4];
            const unsigned int b0 = vcur[vrow + ks * 8 + tg];
            const unsigned int b1 = vcur[vrow + ks * 8 + tg + 4];
            mma_f16(cc0, cc1, cc2, cc3, a0, a1, a2, a3, b0, b1);
        }
        if (kb < 15) {
            #pragma unroll
            for (int j = 0; j < 8; ++j) {
                const int i = t + j * 512;
                const int d = i & 63, kp = i >> 6;
                vnxt[d * VKP + kp] = pack_f16(vf0[j], vf1[j]);
            }
        }
        __syncthreads();
    }
    {
        const int r0 = mt2 * 16 + g;
        const int d0 = dbase + 2 * tg;
        const float i0 = inv[r0], i1 = inv[r0 + 8];
        float* c0p = ctx_out + ((size_t)b * SS + q0 + r0) * DM + h * DH + d0;
        float* c1p = ctx_out + ((size_t)b * SS + q0 + r0 + 8) * DM + h * DH + d0;
        c0p[0] = cc0 * i0; c0p[1] = cc1 * i0;
        c1p[0] = cc2 * i1; c1p[1] = cc3 * i1;
    }
}

// ============================================================================
// LayerNorm over last dim (512), one block (128 threads) per row
// ============================================================================
__global__ __launch_bounds__(128) void ln512(
        const float* __restrict__ x, const float* __restrict__ gamma,
        const float* __restrict__ beta, float* __restrict__ out) {
    __shared__ float sh[8];
    const int row = blockIdx.x;
    const int t = threadIdx.x;
    const float* xr = x + (size_t)row * DM;
    float4 v = *(const float4*)(xr + t * 4);
    float s  = v.x + v.y + v.z + v.w;
    float s2 = v.x * v.x + v.y * v.y + v.z * v.z + v.w * v.w;
    #pragma unroll
    for (int off = 16; off; off >>= 1) {
        s  += __shfl_xor_sync(0xffffffffu, s,  off);
        s2 += __shfl_xor_sync(0xffffffffu, s2, off);
    }
    if ((t & 31) == 0) { sh[t >> 5] = s; sh[4 + (t >> 5)] = s2; }
    __syncthreads();
    s  = sh[0] + sh[1] + sh[2] + sh[3];
    s2 = sh[4] + sh[5] + sh[6] + sh[7];
    const float mean = s * (1.0f / 512.0f);
    const float var  = s2 * (1.0f / 512.0f) - mean * mean;
    const float r    = rsqrtf(var + 1e-5f);
    float4 gv = *(const float4*)(gamma + t * 4);
    float4 bv = *(const float4*)(beta + t * 4);
    float4 o;
    o.x = (v.x - mean) * r * gv.x + bv.x;
    o.y = (v.y - mean) * r * gv.y + bv.y;
    o.z = (v.z - mean) * r * gv.z + bv.z;
    o.w = (v.w - mean) * r * gv.w + bv.w;
    *(float4*)(out + (size_t)row * DM + t * 4) = o;
}

// ============================================================================
extern "C" void kernel_launch(void* const* d_in, const int* in_sizes, int n_in,
                              void* d_out, int out_size) {
    (void)in_sizes; (void)n_in; (void)out_size;
    const float* input_Q = (const float*)d_in[0];
    const float* input_K = (const float*)d_in[1];
    const float* input_V = (const float*)d_in[2];
    const void*  mask    = d_in[3];
    const float* W_Q     = (const float*)d_in[4];
    const float* W_K     = (const float*)d_in[5];
    // d_in[6] = W_V intentionally unused (reference bug: V projected with W_K)
    const float* W_fc    = (const float*)d_in[7];
    const float* gamma   = (const float*)d_in[8];
    const float* beta    = (const float*)d_in[9];

    float* out      = (float*)d_out;
    float* normed   = out;
    float* attn_out = out + (size_t)BB * SS * DM;

    float *Qp, *Kp, *Vp, *ctx, *x;
    cudaGetSymbolAddress((void**)&Qp,  g_Qp);
    cudaGetSymbolAddress((void**)&Kp,  g_Kp);
    cudaGetSymbolAddress((void**)&Vp,  g_Vp);
    cudaGetSymbolAddress((void**)&ctx, g_ctx);
    cudaGetSymbolAddress((void**)&x,   g_x);

    detect_mask_mode<<<1, 32>>>((const unsigned int*)mask);

    cudaFuncSetAttribute(gemm_tf32<3>,
                         cudaFuncAttributeMaxDynamicSharedMemorySize, GEMM_SMEM_3);
    cudaFuncSetAttribute(gemm_tf32<1>,
                         cudaFuncAttributeMaxDynamicSharedMemorySize, GEMM_SMEM_1);

    const dim3 gg(DM / 64, (BB * SS) / 128);   // 8 x 64
    gemm_tf32<3><<<gg, 256, GEMM_SMEM_3>>>(input_Q, W_Q, nullptr, Qp);
    gemm_tf32<3><<<gg, 256, GEMM_SMEM_3>>>(input_K, W_K, nullptr, Kp);
    gemm_tf32<1><<<gg, 256, GEMM_SMEM_1>>>(input_V, W_K, nullptr, Vp);  // W_K bug

    cudaFuncSetAttribute(attn_mma,
                         cudaFuncAttributeMaxDynamicSharedMemorySize, ATT_SMEM_BYTES);
    attn_mma<<<dim3(SS / 32, BB * HH), 512, ATT_SMEM_BYTES>>>(
        Qp, Kp, Vp, mask, attn_out, ctx);

    gemm_tf32<1><<<gg, 256, GEMM_SMEM_1>>>(ctx, W_fc, input_Q, x);  // fused residual
    ln512<<<BB * SS, 128>>>(x, gamma, beta, normed);
}

// round 15
// speedup vs baseline: 2.8881x; 1.0142x over previous
#include <cuda_runtime.h>
#include <cuda_bf16.h>
#include <cuda_fp16.h>

#define BB 4
#define HH 8
#define SS 2048
#define DM 512
#define DH 64

// ---- scratch (static device allocs: allowed; cudaMalloc is not) ----
__device__ float g_Qp[BB*SS*DM];
__device__ float g_Kp[BB*SS*DM];
__device__ float g_Vp[BB*SS*DM];
__device__ float g_ctx[BB*SS*DM];
__device__ float g_x[BB*SS*DM];
__device__ int   g_mask_mode;   // 0=uint8, 1=float32, 2=int32

__global__ void detect_mask_mode(const unsigned int* __restrict__ m) {
    if (threadIdx.x == 0) {
        bool f01 = true, i01 = true;
        for (int i = 0; i < 1024; ++i) {
            const unsigned int w = m[i];
            if (w != 0u && w != 0x3F800000u) f01 = false;
            if (w != 0u && w != 1u)          i01 = false;
        }
        g_mask_mode = f01 ? 1 : (i01 ? 2 : 0);
    }
}

// ---------------------------------------------------------------------------
// mma / async helpers
// ---------------------------------------------------------------------------
__device__ __forceinline__ unsigned int f2tf32(float x) {
    unsigned int u;
    asm("cvt.rna.tf32.f32 %0, %1;" : "=r"(u) : "f"(x));
    return u;
}
__device__ __forceinline__ unsigned int pack_f16(float lo, float hi) {
    unsigned int u;
    asm("cvt.rn.f16x2.f32 %0, %1, %2;" : "=r"(u) : "f"(hi), "f"(lo));
    return u;
}
__device__ __forceinline__ void mma_tf32(float& c0, float& c1, float& c2, float& c3,
        unsigned int a0, unsigned int a1, unsigned int a2, unsigned int a3,
        unsigned int b0, unsigned int b1) {
    asm volatile(
        "mma.sync.aligned.m16n8k8.row.col.f32.tf32.tf32.f32 "
        "{%0,%1,%2,%3}, {%4,%5,%6,%7}, {%8,%9}, {%0,%1,%2,%3};\n"
        : "+f"(c0), "+f"(c1), "+f"(c2), "+f"(c3)
        : "r"(a0), "r"(a1), "r"(a2), "r"(a3), "r"(b0), "r"(b1));
}
__device__ __forceinline__ void mma_f16(float& c0, float& c1, float& c2, float& c3,
        unsigned int a0, unsigned int a1, unsigned int a2, unsigned int a3,
        unsigned int b0, unsigned int b1) {
    asm volatile(
        "mma.sync.aligned.m16n8k16.row.col.f32.f16.f16.f32 "
        "{%0,%1,%2,%3}, {%4,%5,%6,%7}, {%8,%9}, {%0,%1,%2,%3};\n"
        : "+f"(c0), "+f"(c1), "+f"(c2), "+f"(c3)
        : "r"(a0), "r"(a1), "r"(a2), "r"(a3), "r"(b0), "r"(b1));
}
__device__ __forceinline__ void cp_async16(unsigned int smem_addr, const void* gptr) {
    asm volatile("cp.async.cg.shared.global [%0], [%1], 16;\n"
                 :: "r"(smem_addr), "l"(gptr));
}
__device__ __forceinline__ void cp_commit() {
    asm volatile("cp.async.commit_group;\n");
}
template<int N>
__device__ __forceinline__ void cp_wait() {
    asm volatile("cp.async.wait_group %0;\n" :: "n"(N));
}

// ============================================================================
// tf32 tensor-core GEMM: C[M,512] = A[M,512] @ W[512,512]^T (+resid)
// (unchanged from R8: 45us NP1 / ~90us NP3)
// ============================================================================
#define GPA 68
template<int NP>
__global__ __launch_bounds__(256) void gemm_tf32(
        const float* __restrict__ A, const float* __restrict__ W,
        const float* __restrict__ resid, float* __restrict__ C) {
    extern __shared__ float gsm[];
    float* Ah = gsm;                      // [128][GPA]
    float* Wh = Ah + 128 * GPA;           // [64][GPA]
    float* Al = Wh + 64 * GPA;            // NP==3 only
    float* Wl = Al + 128 * GPA;

    const int t = threadIdx.x, w = t >> 5, l = t & 31;
    const int g = l >> 2, tg = l & 3;
    const int wm = w >> 1, wn = w & 1;
    const int m0 = blockIdx.y * 128, n0 = blockIdx.x * 64;
    const int lrow = t >> 4, lc4 = (t & 15) << 2;

    float acc[2][4][4] = {};

    float4 areg[8], wreg[4];
    #pragma unroll
    for (int j = 0; j < 8; ++j)
        areg[j] = *(const float4*)(A + (size_t)(m0 + lrow + j * 16) * 512 + lc4);
    #pragma unroll
    for (int j = 0; j < 4; ++j)
        wreg[j] = *(const float4*)(W + (size_t)(n0 + lrow + j * 16) * 512 + lc4);

    for (int kc = 0; kc < 8; ++kc) {
        __syncthreads();
        #pragma unroll
        for (int j = 0; j < 8; ++j) {
            float* dh = Ah + (lrow + j * 16) * GPA + lc4;
            const float4 v = areg[j];
            const float hx = __uint_as_float(f2tf32(v.x));
            const float hy = __uint_as_float(f2tf32(v.y));
            const float hz = __uint_as_float(f2tf32(v.z));
            const float hw = __uint_as_float(f2tf32(v.w));
            dh[0] = hx; dh[1] = hy; dh[2] = hz; dh[3] = hw;
            if (NP == 3) {
                float* dl = Al + (lrow + j * 16) * GPA + lc4;
                dl[0] = __uint_as_float(f2tf32(v.x - hx));
                dl[1] = __uint_as_float(f2tf32(v.y - hy));
                dl[2] = __uint_as_float(f2tf32(v.z - hz));
                dl[3] = __uint_as_float(f2tf32(v.w - hw));
            }
        }
        #pragma unroll
        for (int j = 0; j < 4; ++j) {
            float* dh = Wh + (lrow + j * 16) * GPA + lc4;
            const float4 v = wreg[j];
            const float hx = __uint_as_float(f2tf32(v.x));
            const float hy = __uint_as_float(f2tf32(v.y));
            const float hz = __uint_as_float(f2tf32(v.z));
            const float hw = __uint_as_float(f2tf32(v.w));
            dh[0] = hx; dh[1] = hy; dh[2] = hz; dh[3] = hw;
            if (NP == 3) {
                float* dl = Wl + (lrow + j * 16) * GPA + lc4;
                dl[0] = __uint_as_float(f2tf32(v.x - hx));
                dl[1] = __uint_as_float(f2tf32(v.y - hy));
                dl[2] = __uint_as_float(f2tf32(v.z - hz));
                dl[3] = __uint_as_float(f2tf32(v.w - hw));
            }
        }
        __syncthreads();
        if (kc < 7) {
            const int k4 = (kc + 1) * 64 + lc4;
            #pragma unroll
            for (int j = 0; j < 8; ++j)
                areg[j] = *(const float4*)(A + (size_t)(m0 + lrow + j * 16) * 512 + k4);
            #pragma unroll
            for (int j = 0; j < 4; ++j)
                wreg[j] = *(const float4*)(W + (size_t)(n0 + lrow + j * 16) * 512 + k4);
        }
        #pragma unroll
        for (int ks = 0; ks < 8; ++ks) {
            unsigned int ah[2][4], bh[4][2];
            #pragma unroll
            for (int mt = 0; mt < 2; ++mt) {
                const int r = wm * 32 + mt * 16;
                ah[mt][0] = __float_as_uint(Ah[(r + g) * GPA + ks * 8 + tg]);
                ah[mt][1] = __float_as_uint(Ah[(r + g + 8) * GPA + ks * 8 + tg]);
                ah[mt][2] = __float_as_uint(Ah[(r + g) * GPA + ks * 8 + tg + 4]);
                ah[mt][3] = __float_as_uint(Ah[(r + g + 8) * GPA + ks * 8 + tg + 4]);
            }
            #pragma unroll
            for (int nt = 0; nt < 4; ++nt) {
                const int r = wn * 32 + nt * 8 + g;
                bh[nt][0] = __float_as_uint(Wh[r * GPA + ks * 8 + tg]);
                bh[nt][1] = __float_as_uint(Wh[r * GPA + ks * 8 + tg + 4]);
            }
            #pragma unroll
            for (int mt = 0; mt < 2; ++mt)
                #pragma unroll
                for (int nt = 0; nt < 4; ++nt)
                    mma_tf32(acc[mt][nt][0], acc[mt][nt][1], acc[mt][nt][2], acc[mt][nt][3],
                             ah[mt][0], ah[mt][1], ah[mt][2], ah[mt][3],
                             bh[nt][0], bh[nt][1]);
            if (NP == 3) {
                unsigned int bl[4][2];
                #pragma unroll
                for (int nt = 0; nt < 4; ++nt) {
                    const int r = wn * 32 + nt * 8 + g;
                    bl[nt][0] = __float_as_uint(Wl[r * GPA + ks * 8 + tg]);
                    bl[nt][1] = __float_as_uint(Wl[r * GPA + ks * 8 + tg + 4]);
                }
                #pragma unroll
                for (int mt = 0; mt < 2; ++mt)
                    #pragma unroll
                    for (int nt = 0; nt < 4; ++nt)
                        mma_tf32(acc[mt][nt][0], acc[mt][nt][1], acc[mt][nt][2], acc[mt][nt][3],
                                 ah[mt][0], ah[mt][1], ah[mt][2], ah[mt][3],
                                 bl[nt][0], bl[nt][1]);
                unsigned int al[2][4];
                #pragma unroll
                for (int mt = 0; mt < 2; ++mt) {
                    const int r = wm * 32 + mt * 16;
                    al[mt][0] = __float_as_uint(Al[(r + g) * GPA + ks * 8 + tg]);
                    al[mt][1] = __float_as_uint(Al[(r + g + 8) * GPA + ks * 8 + tg]);
                    al[mt][2] = __float_as_uint(Al[(r + g) * GPA + ks * 8 + tg + 4]);
                    al[mt][3] = __float_as_uint(Al[(r + g + 8) * GPA + ks * 8 + tg + 4]);
                }
                #pragma unroll
                for (int mt = 0; mt < 2; ++mt)
                    #pragma unroll
                    for (int nt = 0; nt < 4; ++nt)
                        mma_tf32(acc[mt][nt][0], acc[mt][nt][1], acc[mt][nt][2], acc[mt][nt][3],
                                 al[mt][0], al[mt][1], al[mt][2], al[mt][3],
                                 bh[nt][0], bh[nt][1]);
            }
        }
    }
    // epilogue
    #pragma unroll
    for (int mt = 0; mt < 2; ++mt) {
        const int mA = m0 + wm * 32 + mt * 16 + g;
        const int mB = mA + 8;
        #pragma unroll
        for (int nt = 0; nt < 4; ++nt) {
            const int n = n0 + wn * 32 + nt * 8 + 2 * tg;
            float v0 = acc[mt][nt][0], v1 = acc[mt][nt][1];
            float v2 = acc[mt][nt][2], v3 = acc[mt][nt][3];
            if (resid) {
                const float2 r0 = *(const float2*)(resid + (size_t)mA * 512 + n);
                const float2 r1 = *(const float2*)(resid + (size_t)mB * 512 + n);
                v0 += r0.x; v1 += r0.y; v2 += r1.x; v3 += r1.y;
            }
            *(float2*)(C + (size_t)mA * 512 + n) = make_float2(v0, v1);
            *(float2*)(C + (size_t)mB * 512 + n) = make_float2(v2, v3);
        }
    }
}
#define GEMM_SMEM_1 ((128 + 64) * GPA * 4)
#define GEMM_SMEM_3 (2 * (128 + 64) * GPA * 4)

__device__ __forceinline__ void mask_pair(const void* mask, int mode, size_t off,
                                          bool& m0, bool& m1) {
    if (mode == 1) {
        float2 v = *(const float2*)((const float*)mask + off);
        m0 = v.x != 0.0f; m1 = v.y != 0.0f;
    } else if (mode == 2) {
        int2 v = *(const int2*)((const int*)mask + off);
        m0 = v.x != 0; m1 = v.y != 0;
    } else {
        const unsigned char* p = (const unsigned char*)mask + off;
        m0 = p[0] != 0; m1 = p[1] != 0;
    }
}

// ============================================================================
// Tensor-core fused attention v4: phase-1 K tiles now loaded with cp.async.cg
// (raw fp32; HMMA truncates to tf32 — removes per-iter LDG staging + 16 CVT +
// 16 STS per thread). Double buffering + 1 barrier/iter as in v3. Phase 2
// unchanged (V needs transpose+f16 pack, cp.async inapplicable).
// ============================================================================
#define EPW 1032   // e-strip pitch (half2 words)
#define KP  68     // K tile pitch (floats); row stride 272B = 17*16B (cp.async OK)
#define VKP 69     // Vt pitch (half2 words)
#define QP  68     // Q tile pitch (floats)
#define KBUF (128*KP)   // per-buffer stride (words); Vt (64*VKP=4416) fits too

#define SM_EW    0
#define SM_KT    (32*EPW)
#define SM_QS    (SM_KT + 2*KBUF)
#define SM_RSUM  (SM_QS + 32*QP)
#define SM_INV   (SM_RSUM + 16*32)
#define ATT_WORDS (SM_INV + 32)
#define ATT_SMEM_BYTES (ATT_WORDS * 4)

__global__ __launch_bounds__(512, 1) void attn_mma(
        const float* __restrict__ Qp, const float* __restrict__ Kp,
        const float* __restrict__ Vp, const void* __restrict__ mask,
        float* __restrict__ attn_out, float* __restrict__ ctx_out) {
    extern __shared__ float sm[];
    unsigned int* Ew   = (unsigned int*)sm;
    float*        Kt   = sm + SM_KT;                   // 2 x [128][KP]
    unsigned int* Vtw  = (unsigned int*)(sm + SM_KT);  // 2 x [64][VKP]
    float*        Qs   = sm + SM_QS;
    float*        rowsumW = sm + SM_RSUM;
    float*        inv  = sm + SM_INV;

    const int t = threadIdx.x, w = t >> 5, l = t & 31;
    const int g = l >> 2, tg = l & 3;
    const int bh = blockIdx.y, b = bh >> 3, h = bh & 7;
    const int q0 = blockIdx.x * 32;
    const float* Qb = Qp + (size_t)bh * SS * DH;
    const float* Kb = Kp + (size_t)bh * SS * DH;
    const float* Vb = Vp + (size_t)bh * SS * DH;
    const int mode = g_mask_mode;

    const int lkey = t >> 4, lc4 = (t & 15) << 2;   // K-tile load coords
    // smem byte addresses of this thread's 4 K-chunk slots (per buffer)
    const unsigned int ktBase =
        (unsigned int)__cvta_generic_to_shared(Kt) ;

    // ---- kick off cp.async for K tile 0 (overlaps Q load below) ----
    #pragma unroll
    for (int j = 0; j < 4; ++j)
        cp_async16(ktBase + (unsigned int)(((lkey + j * 32) * KP + lc4) * 4),
                   Kb + (size_t)(lkey + j * 32) * DH + lc4);
    cp_commit();

    for (int i = t; i < 32 * 64; i += 512) {
        const int r = i >> 6, c = i & 63;
        Qs[r * QP + c] = Qb[(size_t)(q0 + r) * DH + c];
    }
    __syncthreads();

    // ---- Q fragments: kb-invariant (rna-rounded tf32) ----
    unsigned int A2[2][8][4];
    #pragma unroll
    for (int mt = 0; mt < 2; ++mt)
        #pragma unroll
        for (int ks = 0; ks < 8; ++ks) {
            A2[mt][ks][0] = f2tf32(Qs[(mt * 16 + g) * QP + ks * 8 + tg]);
            A2[mt][ks][1] = f2tf32(Qs[(mt * 16 + g + 8) * QP + ks * 8 + tg]);
            A2[mt][ks][2] = f2tf32(Qs[(mt * 16 + g) * QP + ks * 8 + tg + 4]);
            A2[mt][ks][3] = f2tf32(Qs[(mt * 16 + g + 8) * QP + ks * 8 + tg + 4]);
        }

    float rs[4] = {0, 0, 0, 0};

    // tile 0 complete + visible to all threads
    cp_wait<0>();
    __syncthreads();

    // ================= Phase 1: scores + exp (cp.async double-buffered) =====
    for (int kb = 0; kb < 16; ++kb) {
        const float* cur = Kt + (kb & 1) * KBUF;
        const unsigned int nxtB = ktBase + (unsigned int)((((kb + 1) & 1) * KBUF) * 4);
        if (kb < 15) {
            // issue next tile immediately; latency hides under mma+exp
            #pragma unroll
            for (int j = 0; j < 4; ++j)
                cp_async16(nxtB + (unsigned int)(((lkey + j * 32) * KP + lc4) * 4),
                           Kb + (size_t)((kb + 1) * 128 + lkey + j * 32) * DH + lc4);
            cp_commit();
        }
        // hoisted mask loads (latency hidden under mma)
        const int kcol = kb * 128 + w * 8 + 2 * tg;
        bool mm[2][4];
        #pragma unroll
        for (int mt = 0; mt < 2; ++mt) {
            const int r0 = q0 + mt * 16 + g;
            mask_pair(mask, mode, ((size_t)b * SS + r0) * SS + kcol, mm[mt][0], mm[mt][1]);
            mask_pair(mask, mode, ((size_t)b * SS + r0 + 8) * SS + kcol, mm[mt][2], mm[mt][3]);
        }
        const int krow = (w * 8 + g) * KP;
        #pragma unroll
        for (int mt = 0; mt < 2; ++mt) {
            float c0 = 0, c1 = 0, c2 = 0, c3 = 0;
            #pragma unroll
            for (int ks = 0; ks < 8; ++ks) {
                const unsigned int b0 = __float_as_uint(cur[krow + ks * 8 + tg]);
                const unsigned int b1 = __float_as_uint(cur[krow + ks * 8 + tg + 4]);
                mma_tf32(c0, c1, c2, c3,
                         A2[mt][ks][0], A2[mt][ks][1], A2[mt][ks][2], A2[mt][ks][3],
                         b0, b1);
            }
            const float e0 = mm[mt][0] ? 0.0f : __expf(c0 * 0.125f);
            const float e1 = mm[mt][1] ? 0.0f : __expf(c1 * 0.125f);
            const float e2 = mm[mt][2] ? 0.0f : __expf(c2 * 0.125f);
            const float e3 = mm[mt][3] ? 0.0f : __expf(c3 * 0.125f);
            const int wcol = kb * 64 + w * 4 + tg;
            Ew[(mt * 16 + g) * EPW + wcol]     = pack_f16(e0, e1);
            Ew[(mt * 16 + g + 8) * EPW + wcol] = pack_f16(e2, e3);
            rs[mt * 2]     += e0 + e1;
            rs[mt * 2 + 1] += e2 + e3;
        }
        if (kb < 15) cp_wait<0>();
        __syncthreads();
    }

    // ---- rowsum reduce ----
    #pragma unroll
    for (int i = 0; i < 4; ++i) {
        rs[i] += __shfl_xor_sync(0xffffffffu, rs[i], 1);
        rs[i] += __shfl_xor_sync(0xffffffffu, rs[i], 2);
    }
    if (tg == 0) {
        rowsumW[w * 32 + g]      = rs[0];
        rowsumW[w * 32 + g + 8]  = rs[1];
        rowsumW[w * 32 + g + 16] = rs[2];
        rowsumW[w * 32 + g + 24] = rs[3];
    }
    // issue first V-tile loads early (latency hidden under inv computation)
    float vf0[8], vf1[8];
    #pragma unroll
    for (int j = 0; j < 8; ++j) {
        const int i = t + j * 512;
        const int d = i & 63, kp = i >> 6;
        vf0[j] = Vb[(size_t)(2 * kp) * DH + d];
        vf1[j] = Vb[(size_t)(2 * kp + 1) * DH + d];
    }
    __syncthreads();
    if (t < 32) {
        float s = 0.0f;
        #pragma unroll
        for (int ww = 0; ww < 16; ++ww) s += rowsumW[ww * 32 + t];
        inv[t] = 1.0f / s;
    }
    __syncthreads();

    // ================= Phase 2: ctx = (e @ V) * inv (double-buffered Vt) ====
    #pragma unroll
    for (int j = 0; j < 8; ++j) {
        const int i = t + j * 512;
        const int d = i & 63, kp = i >> 6;
        Vtw[d * VKP + kp] = pack_f16(vf0[j], vf1[j]);
    }
    __syncthreads();

    const int mt2 = w >> 3, dbase = (w & 7) * 8;
    float cc0 = 0, cc1 = 0, cc2 = 0, cc3 = 0;
    float* abase = attn_out + ((size_t)bh * SS + q0) * SS;

    for (int kb = 0; kb < 16; ++kb) {
        const unsigned int* vcur = Vtw + (kb & 1) * KBUF;
        unsigned int*       vnxt = Vtw + ((kb + 1) & 1) * KBUF;
        if (kb < 15) {
            #pragma unroll
            for (int j = 0; j < 8; ++j) {
                const int i = t + j * 512;
                const int d = i & 63, kp = i >> 6;
                vf0[j] = Vb[(size_t)((kb + 1) * 128 + 2 * kp) * DH + d];
                vf1[j] = Vb[(size_t)((kb + 1) * 128 + 2 * kp + 1) * DH + d];
            }
        }
        // attn write for this tile (2 float4 per thread), overlaps mma below
        #pragma unroll
        for (int j = 0; j < 2; ++j) {
            const int idx = t + j * 512;
            const int r = idx >> 5, c = idx & 31;
            const unsigned int w0 = Ew[r * EPW + kb * 64 + c * 2];
            const unsigned int w1 = Ew[r * EPW + kb * 64 + c * 2 + 1];
            const half2 h0 = *(const half2*)&w0;
            const half2 h1 = *(const half2*)&w1;
            const float iv = inv[r];
            float4 o;
            o.x = __half2float(h0.x) * iv;
            o.y = __half2float(h0.y) * iv;
            o.z = __half2float(h1.x) * iv;
            o.w = __half2float(h1.y) * iv;
            *(float4*)(abase + (size_t)r * SS + kb * 128 + c * 4) = o;
        }
        const int arow0 = (mt2 * 16 + g) * EPW + kb * 64;
        const int arow1 = (mt2 * 16 + g + 8) * EPW + kb * 64;
        const int vrow  = (dbase + g) * VKP;
        #pragma unroll
        for (int ks = 0; ks < 8; ++ks) {
            const unsigned int a0 = Ew[arow0 + ks * 8 + tg];
            const unsigned int a1 = Ew[arow1 + ks * 8 + tg];
            const unsigned int a2 = Ew[arow0 + ks * 8 + tg + 4];
            const unsigned int a3 = Ew[arow1 + ks * 8 + tg + 4];
            const unsigned int b0 = vcur[vrow + ks * 8 + tg];
            const unsigned int b1 = vcur[vrow + ks * 8 + tg + 4];
            mma_f16(cc0, cc1, cc2, cc3, a0, a1, a2, a3, b0, b1);
        }
        if (kb < 15) {
            #pragma unroll
            for (int j = 0; j < 8; ++j) {
                const int i = t + j * 512;
                const int d = i & 63, kp = i >> 6;
                vnxt[d * VKP + kp] = pack_f16(vf0[j], vf1[j]);
            }
        }
        __syncthreads();
    }
    {
        const int r0 = mt2 * 16 + g;
        const int d0 = dbase + 2 * tg;
        const float i0 = inv[r0], i1 = inv[r0 + 8];
        float* c0p = ctx_out + ((size_t)b * SS + q0 + r0) * DM + h * DH + d0;
        float* c1p = ctx_out + ((size_t)b * SS + q0 + r0 + 8) * DM + h * DH + d0;
        c0p[0] = cc0 * i0; c0p[1] = cc1 * i0;
        c1p[0] = cc2 * i1; c1p[1] = cc3 * i1;
    }
}

// ============================================================================
// LayerNorm over last dim (512), one block (128 threads) per row
// ============================================================================
__global__ __launch_bounds__(128) void ln512(
        const float* __restrict__ x, const float* __restrict__ gamma,
        const float* __restrict__ beta, float* __restrict__ out) {
    __shared__ float sh[8];
    const int row = blockIdx.x;
    const int t = threadIdx.x;
    const float* xr = x + (size_t)row * DM;
    float4 v = *(const float4*)(xr + t * 4);
    float s  = v.x + v.y + v.z + v.w;
    float s2 = v.x * v.x + v.y * v.y + v.z * v.z + v.w * v.w;
    #pragma unroll
    for (int off = 16; off; off >>= 1) {
        s  += __shfl_xor_sync(0xffffffffu, s,  off);
        s2 += __shfl_xor_sync(0xffffffffu, s2, off);
    }
    if ((t & 31) == 0) { sh[t >> 5] = s; sh[4 + (t >> 5)] = s2; }
    __syncthreads();
    s  = sh[0] + sh[1] + sh[2] + sh[3];
    s2 = sh[4] + sh[5] + sh[6] + sh[7];
    const float mean = s * (1.0f / 512.0f);
    const float var  = s2 * (1.0f / 512.0f) - mean * mean;
    const float r    = rsqrtf(var + 1e-5f);
    float4 gv = *(const float4*)(gamma + t * 4);
    float4 bv = *(const float4*)(beta + t * 4);
    float4 o;
    o.x = (v.x - mean) * r * gv.x + bv.x;
    o.y = (v.y - mean) * r * gv.y + bv.y;
    o.z = (v.z - mean) * r * gv.z + bv.z;
    o.w = (v.w - mean) * r * gv.w + bv.w;
    *(float4*)(out + (size_t)row * DM + t * 4) = o;
}

// ============================================================================
extern "C" void kernel_launch(void* const* d_in, const int* in_sizes, int n_in,
                              void* d_out, int out_size) {
    (void)in_sizes; (void)n_in; (void)out_size;
    const float* input_Q = (const float*)d_in[0];
    const float* input_K = (const float*)d_in[1];
    const float* input_V = (const float*)d_in[2];
    const void*  mask    = d_in[3];
    const float* W_Q     = (const float*)d_in[4];
    const float* W_K     = (const float*)d_in[5];
    // d_in[6] = W_V intentionally unused (reference bug: V projected with W_K)
    const float* W_fc    = (const float*)d_in[7];
    const float* gamma   = (const float*)d_in[8];
    const float* beta    = (const float*)d_in[9];

    float* out      = (float*)d_out;
    float* normed   = out;
    float* attn_out = out + (size_t)BB * SS * DM;

    float *Qp, *Kp, *Vp, *ctx, *x;
    cudaGetSymbolAddress((void**)&Qp,  g_Qp);
    cudaGetSymbolAddress((void**)&Kp,  g_Kp);
    cudaGetSymbolAddress((void**)&Vp,  g_Vp);
    cudaGetSymbolAddress((void**)&ctx, g_ctx);
    cudaGetSymbolAddress((void**)&x,   g_x);

    detect_mask_mode<<<1, 32>>>((const unsigned int*)mask);

    cudaFuncSetAttribute(gemm_tf32<3>,
                         cudaFuncAttributeMaxDynamicSharedMemorySize, GEMM_SMEM_3);
    cudaFuncSetAttribute(gemm_tf32<1>,
                         cudaFuncAttributeMaxDynamicSharedMemorySize, GEMM_SMEM_1);

    const dim3 gg(DM / 64, (BB * SS) / 128);   // 8 x 64
    gemm_tf32<3><<<gg, 256, GEMM_SMEM_3>>>(input_Q, W_Q, nullptr, Qp);
    gemm_tf32<3><<<gg, 256, GEMM_SMEM_3>>>(input_K, W_K, nullptr, Kp);
    gemm_tf32<1><<<gg, 256, GEMM_SMEM_1>>>(input_V, W_K, nullptr, Vp);  // W_K bug

    cudaFuncSetAttribute(attn_mma,
                         cudaFuncAttributeMaxDynamicSharedMemorySize, ATT_SMEM_BYTES);
    attn_mma<<<dim3(SS / 32, BB * HH), 512, ATT_SMEM_BYTES>>>(
        Qp, Kp, Vp, mask, attn_out, ctx);

    gemm_tf32<1><<<gg, 256, GEMM_SMEM_1>>>(ctx, W_fc, input_Q, x);  // fused residual
    ln512<<<BB * SS, 128>>>(x, gamma, beta, normed);
}